// round 12
// baseline (speedup 1.0000x reference)
#include <cuda_runtime.h>
#include <cuda_fp16.h>
#include <math.h>
#include <stdint.h>

#define NNODES 50000
#define NEDGES 500000
#define FDIM   128
#define CLS    40

// ---------------- scratch (static device globals; no allocation) ------------
__device__ float  g_A   [NNODES * FDIM];   // A' = x @ W_top + b_pre (fp32)
__device__ __half g_Bh  [NNODES * FDIM];   // B  = x @ W_bot        (fp16)
__device__ float  g_S   [NNODES * FDIM];   // SUM aggregator  (fp32)
__device__ float  g_M   [NNODES * FDIM];   // MAX aggregator  (fp32)
__device__ float  g_H   [NNODES * FDIM];   // hidden after layer 1 (fp32)
__device__ float  g_H2  [NNODES * FDIM];   // hidden after layer 2 (fp32)
__device__ float  g_IC  [NNODES + 128];    // 1/max(cnt,1) per node (padded)
__device__ __half g_WpreH[2 * 2 * FDIM * FDIM]; // [layer][half][n][k] fp16 transposed
__device__ __half g_WfT1[FDIM * 512];      // fused W' layer 1, [n][k] fp16 transposed
__device__ __half g_WfT2[FDIM * 512];      // fused W' layer 2, [n][k] fp16 transposed
__device__ float  g_Wfb1[FDIM];            // fused bias layer 1 (fp32)
__device__ float  g_Wfb2[FDIM];            // fused bias layer 2 (fp32)
__device__ float  g_WoR [FDIM * CLS];      // tf32-rounded w_out (fp32)
__device__ int    g_hist[NNODES];
__device__ int    g_off [NNODES + 1];
__device__ int    g_cur [NNODES];
__device__ int    g_ssrc[NEDGES];          // src ids grouped (counting-sorted) by dst

// ---------------- helpers ---------------------------------------------------
__device__ __forceinline__ float tf32r(float x) {
    unsigned u;
    asm("cvt.rna.tf32.f32 %0, %1;" : "=r"(u) : "f"(x));
    return __uint_as_float(u);
}

__device__ __forceinline__ unsigned tf32u(float x) {
    unsigned u;
    asm("cvt.rna.tf32.f32 %0, %1;" : "=r"(u) : "f"(x));
    return u;
}

__device__ __forceinline__ unsigned pack_h2(float lo, float hi) {
    __half2 h = __floats2half2_rn(lo, hi);   // .x = lo (low 16 bits) = lower k
    return *reinterpret_cast<unsigned*>(&h);
}

__device__ __forceinline__ void cpasync16(void* dst, const void* src, bool pred) {
    unsigned sa = (unsigned)__cvta_generic_to_shared(dst);
    int sz = pred ? 16 : 0;
    asm volatile("cp.async.cg.shared.global [%0], [%1], 16, %2;\n"
                 :: "r"(sa), "l"(src), "r"(sz));
}

// fp16 MMA, fp32 accumulate: D(16x8) += A(16x16) * B(16x8)
__device__ __forceinline__ void mma_f16(float* c, const unsigned* a,
                                        unsigned b0, unsigned b1) {
    asm volatile(
        "mma.sync.aligned.m16n8k16.row.col.f32.f16.f16.f32 "
        "{%0,%1,%2,%3}, {%4,%5,%6,%7}, {%8,%9}, {%0,%1,%2,%3};"
        : "+f"(c[0]), "+f"(c[1]), "+f"(c[2]), "+f"(c[3])
        : "r"(a[0]), "r"(a[1]), "r"(a[2]), "r"(a[3]), "r"(b0), "r"(b1));
}

// tf32 MMA (kept for the small output projection)
__device__ __forceinline__ void mma_tf32(float* c, const unsigned* a,
                                         unsigned b0, unsigned b1) {
    asm volatile(
        "mma.sync.aligned.m16n8k8.row.col.f32.tf32.tf32.f32 "
        "{%0,%1,%2,%3}, {%4,%5,%6,%7}, {%8,%9}, {%0,%1,%2,%3};"
        : "+f"(c[0]), "+f"(c[1]), "+f"(c[2]), "+f"(c[3])
        : "r"(a[0]), "r"(a[1]), "r"(a[2]), "r"(a[3]), "r"(b0), "r"(b1));
}

// ---------------- graph preprocessing ---------------------------------------
__global__ void hist_kernel(const int* __restrict__ dst) {
    int i = blockIdx.x * blockDim.x + threadIdx.x;
    if (i < NEDGES) atomicAdd(&g_hist[dst[i]], 1);
}

__global__ void scan_kernel() {  // 1 block, 1024 threads
    __shared__ int s[1024];
    const int t = threadIdx.x;
    const int chunk = (NNODES + 1023) / 1024;
    int beg = t * chunk;
    int end = beg + chunk; if (end > NNODES) end = NNODES;
    int sum = 0;
    for (int i = beg; i < end; i++) sum += g_hist[i];
    s[t] = sum;
    __syncthreads();
    for (int d = 1; d < 1024; d <<= 1) {
        int v = (t >= d) ? s[t - d] : 0;
        __syncthreads();
        s[t] += v;
        __syncthreads();
    }
    int run = (t > 0) ? s[t - 1] : 0;
    for (int i = beg; i < end; i++) { g_off[i] = run; run += g_hist[i]; }
    if (t == 0) g_off[NNODES] = NEDGES;
}

__global__ void scatter_kernel(const int* __restrict__ src, const int* __restrict__ dst) {
    int i = blockIdx.x * blockDim.x + threadIdx.x;
    if (i >= NEDGES) return;
    int d = dst[i];
    int p = g_off[d] + atomicAdd(&g_cur[d], 1);
    g_ssrc[p] = src[i];
}

// ---------------- weight preprocessing ---------------------------------------
#define PREP_W  (2 * 2 * FDIM * FDIM)           // 65536
#define PREP_O  (FDIM * CLS)                    // 5120
__global__ void prep_weights(const float* __restrict__ w1,
                             const float* __restrict__ w2,
                             const float* __restrict__ wo) {
    int i = blockIdx.x * blockDim.x + threadIdx.x;
    if (i < PREP_W) {
        int k = i & 127;
        int n = (i >> 7) & 127;
        int h = (i >> 14) & 1;
        int l = i >> 15;
        const float* w = l ? w2 : w1;
        g_WpreH[i] = __float2half_rn(__ldg(&w[(h * 128 + k) * 128 + n]));
    } else if (i < PREP_W + PREP_O) {
        int j = i - PREP_W;
        g_WoR[j] = tf32r(wo[j]);
    }
}

// ---------------- aggregation (warp/node, fp16 gather, unroll 4) --------------
// B rows are fp16 (256B/row): one LDG.64 per lane per edge (4 cols/lane).
// Sum/max accumulate in fp32; sum = cnt*A'(fp32) + sum(fp16 msgs).
__global__ void aggregate_kernel() {
    int node = (blockIdx.x * blockDim.x + threadIdx.x) >> 5;
    if (node >= NNODES) return;
    int lane = threadIdx.x & 31;
    int beg = g_off[node], end = g_off[node + 1];
    const uint2* Bv = (const uint2*)g_Bh;        // 32 uint2 (8B) per row
    float4 s = make_float4(0.f, 0.f, 0.f, 0.f);
    float4 m = make_float4(-3.4e38f, -3.4e38f, -3.4e38f, -3.4e38f);
    int e = beg;
    for (; e + 3 < end; e += 4) {
        int sv0 = __ldg(&g_ssrc[e]);
        int sv1 = __ldg(&g_ssrc[e + 1]);
        int sv2 = __ldg(&g_ssrc[e + 2]);
        int sv3 = __ldg(&g_ssrc[e + 3]);
        uint2 r0 = __ldg(&Bv[(size_t)sv0 * 32 + lane]);
        uint2 r1 = __ldg(&Bv[(size_t)sv1 * 32 + lane]);
        uint2 r2 = __ldg(&Bv[(size_t)sv2 * 32 + lane]);
        uint2 r3 = __ldg(&Bv[(size_t)sv3 * 32 + lane]);
        float2 a0 = __half22float2(*(__half2*)&r0.x);
        float2 b0 = __half22float2(*(__half2*)&r0.y);
        float2 a1 = __half22float2(*(__half2*)&r1.x);
        float2 b1 = __half22float2(*(__half2*)&r1.y);
        float2 a2 = __half22float2(*(__half2*)&r2.x);
        float2 b2 = __half22float2(*(__half2*)&r2.y);
        float2 a3 = __half22float2(*(__half2*)&r3.x);
        float2 b3 = __half22float2(*(__half2*)&r3.y);
        s.x += (a0.x + a1.x) + (a2.x + a3.x);
        s.y += (a0.y + a1.y) + (a2.y + a3.y);
        s.z += (b0.x + b1.x) + (b2.x + b3.x);
        s.w += (b0.y + b1.y) + (b2.y + b3.y);
        m.x = fmaxf(m.x, fmaxf(fmaxf(a0.x, a1.x), fmaxf(a2.x, a3.x)));
        m.y = fmaxf(m.y, fmaxf(fmaxf(a0.y, a1.y), fmaxf(a2.y, a3.y)));
        m.z = fmaxf(m.z, fmaxf(fmaxf(b0.x, b1.x), fmaxf(b2.x, b3.x)));
        m.w = fmaxf(m.w, fmaxf(fmaxf(b0.y, b1.y), fmaxf(b2.y, b3.y)));
    }
    for (; e < end; e++) {
        int sv = __ldg(&g_ssrc[e]);
        uint2 r = __ldg(&Bv[(size_t)sv * 32 + lane]);
        float2 a = __half22float2(*(__half2*)&r.x);
        float2 b = __half22float2(*(__half2*)&r.y);
        s.x += a.x; s.y += a.y; s.z += b.x; s.w += b.y;
        m.x = fmaxf(m.x, a.x); m.y = fmaxf(m.y, a.y);
        m.z = fmaxf(m.z, b.x); m.w = fmaxf(m.w, b.y);
    }
    size_t o = (size_t)node * 32 + lane;   // cols 4*lane..4*lane+3
    float c = (float)(end - beg);
    float ic = 1.f / fmaxf(c, 1.f);
    if (lane == 0) g_IC[node] = ic;
    float4 a = ((const float4*)g_A)[o];
    float4 t;
    t.x = fmaf(c, a.x, s.x); t.y = fmaf(c, a.y, s.y);
    t.z = fmaf(c, a.z, s.z); t.w = fmaf(c, a.w, s.w);
    ((float4*)g_S)[o] = t;
    bool nz = (c > 0.f);
    float4 mx;
    mx.x = nz ? (a.x + m.x) : 0.f; mx.y = nz ? (a.y + m.y) : 0.f;
    mx.z = nz ? (a.z + m.z) : 0.f; mx.w = nz ? (a.w + m.w) : 0.f;
    ((float4*)g_M)[o] = mx;
}

// ---------------- fused post@lin weight: tiled, transposed fp16 output -------
__global__ void fuse_kernel(const float* __restrict__ wpost, const float* __restrict__ bpost,
                            const float* __restrict__ wlin,  const float* __restrict__ blin,
                            __half* __restrict__ wfT, float* __restrict__ wfb) {
    __shared__ float srow[8][FDIM];
    const int b = blockIdx.x, c = threadIdx.x;   // 128 threads
    if (b < 64) {
        #pragma unroll
        for (int j = 0; j < 8; j++)
            srow[j][c] = wpost[(size_t)(8 * b + j) * FDIM + c];
        __syncthreads();
        float acc[8] = {};
        #pragma unroll 4
        for (int k = 0; k < FDIM; k++) {
            float wl = wlin[k * FDIM + c];
            #pragma unroll
            for (int j = 0; j < 8; j++) acc[j] = fmaf(srow[j][k], wl, acc[j]);
        }
        #pragma unroll
        for (int j = 0; j < 8; j++)
            wfT[(size_t)c * 512 + 8 * b + j] = __float2half_rn(acc[j]);
    } else {
        srow[0][c] = bpost[c];
        __syncthreads();
        float acc = blin[c];
        #pragma unroll 4
        for (int k = 0; k < FDIM; k++) acc = fmaf(srow[0][k], wlin[k * FDIM + c], acc);
        wfb[c] = acc;
    }
}

// ---------------- fp16 tensor-core GEMM --------------------------------------
// Block 128(M) x 128(N), K-slab 32, 2-stage cp.async. 8 warps 4(M)x2(N).
// A: fp32 smem -> fp16 frags at load. B: transposed fp16 weights in smem.
// Pre mode (gridDim.x==2): block x=0 writes fp32 A'+bias; x=1 writes fp16 B.
#define AST  36              // A smem row stride (fp32)
#define BSTH 72              // B smem row stride (fp16): 64 + 8 pad
#define STGF (128 * AST + 128 * BSTH / 2)   // floats per stage = 9216
#define GSMEM_BYTES (2 * STGF * 4)          // 73728

struct GemmSrcs { const float* s[4]; };

template<bool SCALE>
__device__ __forceinline__ void mma_block_h(const float* __restrict__ As,
                                            const __half* __restrict__ Bs,
                                            float (*acc)[8][4],
                                            int wm, int wn, int fr, int fc,
                                            const float* fs) {
    #pragma unroll
    for (int ks = 0; ks < 32; ks += 16) {
        unsigned a[2][4];
        #pragma unroll
        for (int mt = 0; mt < 2; mt++) {
            int r0 = wm + mt * 16 + fr;
            float2 p0 = *(const float2*)&As[(r0)     * AST + ks + 2 * fc];
            float2 p1 = *(const float2*)&As[(r0 + 8) * AST + ks + 2 * fc];
            float2 p2 = *(const float2*)&As[(r0)     * AST + ks + 2 * fc + 8];
            float2 p3 = *(const float2*)&As[(r0 + 8) * AST + ks + 2 * fc + 8];
            if (SCALE) {
                float f0 = fs[mt * 2], f1 = fs[mt * 2 + 1];
                p0.x *= f0; p0.y *= f0; p2.x *= f0; p2.y *= f0;
                p1.x *= f1; p1.y *= f1; p3.x *= f1; p3.y *= f1;
            }
            a[mt][0] = pack_h2(p0.x, p0.y);
            a[mt][1] = pack_h2(p1.x, p1.y);
            a[mt][2] = pack_h2(p2.x, p2.y);
            a[mt][3] = pack_h2(p3.x, p3.y);
        }
        #pragma unroll
        for (int nt = 0; nt < 8; nt++) {
            int n = wn + nt * 8 + fr;
            unsigned b0 = *(const unsigned*)&Bs[n * BSTH + ks + 2 * fc];
            unsigned b1 = *(const unsigned*)&Bs[n * BSTH + ks + 2 * fc + 8];
            mma_f16(acc[0][nt], a[0], b0, b1);
            mma_f16(acc[1][nt], a[1], b0, b1);
        }
    }
}

__global__ __launch_bounds__(256, 2)
void mma_gemm(GemmSrcs srcs, const __half* __restrict__ W,
              const float* __restrict__ bias0,
              float* outA, __half* outBh,
              const float* __restrict__ icvec, int meanSeg,
              int M, int nIter, int relu, int ldB) {
    extern __shared__ float smem[];
    const int tid = threadIdx.x;
    const int bm = blockIdx.y * 128;

    const __half* Wb = W;
    const float* bias = bias0;
    bool toHalf = false;
    if (gridDim.x == 2 && blockIdx.x == 1) {
        Wb = W + 128 * 128;        // second weight half (transposed block)
        bias = nullptr;
        toHalf = true;
    }

    const int lane = tid & 31, wid = tid >> 5;
    const int wm = (wid >> 1) * 32, wn = (wid & 1) * 64;
    const int fr = lane >> 2, fc = lane & 3;

    float fs[4] = {1.f, 1.f, 1.f, 1.f};
    if (icvec) {
        int r = bm + wm + fr;
        fs[0] = icvec[r];      fs[1] = icvec[r + 8];
        fs[2] = icvec[r + 16]; fs[3] = icvec[r + 24];
    }

    float acc[2][8][4];
    #pragma unroll
    for (int mt = 0; mt < 2; mt++)
        #pragma unroll
        for (int nt = 0; nt < 8; nt++)
            #pragma unroll
            for (int j = 0; j < 4; j++) acc[mt][nt][j] = 0.f;

    auto loadStage = [&](int it, int stage) {
        int k0 = it * 32;
        const float* sp = srcs.s[(k0 >> 7) & 3];
        int kloc = k0 & 127;
        float* As = smem + stage * STGF;
        __half* Bs = (__half*)(As + 128 * AST);
        #pragma unroll
        for (int i = 0; i < 4; i++) {
            int id = tid + 256 * i;
            int arow = id >> 3, c4 = id & 7;
            bool p = (bm + arow) < M;
            cpasync16(As + arow * AST + c4 * 4,
                      sp + (size_t)(bm + arow) * 128 + kloc + c4 * 4, p);
        }
        #pragma unroll
        for (int i = 0; i < 2; i++) {
            int id = tid + 256 * i;
            int n = id >> 2, c4 = id & 3;
            cpasync16(Bs + n * BSTH + c4 * 8,
                      Wb + (size_t)n * ldB + k0 + c4 * 8, true);
        }
        asm volatile("cp.async.commit_group;" ::: "memory");
    };

    loadStage(0, 0);
    for (int it = 0; it < nIter; ++it) {
        int cur = it & 1;
        if (it + 1 < nIter) {
            loadStage(it + 1, cur ^ 1);
            asm volatile("cp.async.wait_group 1;" ::: "memory");
        } else {
            asm volatile("cp.async.wait_group 0;" ::: "memory");
        }
        __syncthreads();

        const float* As = smem + cur * STGF;
        const __half* Bs = (const __half*)(As + 128 * AST);
        bool ms = (((it * 32) >> 7) == meanSeg);
        if (ms) mma_block_h<true >(As, Bs, acc, wm, wn, fr, fc, fs);
        else    mma_block_h<false>(As, Bs, acc, wm, wn, fr, fc, fs);
        __syncthreads();
    }

    #pragma unroll
    for (int mt = 0; mt < 2; mt++) {
        #pragma unroll
        for (int nt = 0; nt < 8; nt++) {
            int r0 = bm + wm + mt * 16 + fr;
            int cc = wn + nt * 8 + 2 * fc;
            float b0 = 0.f, b1 = 0.f;
            if (bias) { b0 = bias[cc]; b1 = bias[cc + 1]; }
            float v0 = acc[mt][nt][0] + b0, v1 = acc[mt][nt][1] + b1;
            float v2 = acc[mt][nt][2] + b0, v3 = acc[mt][nt][3] + b1;
            if (relu) {
                v0 = fmaxf(v0, 0.f); v1 = fmaxf(v1, 0.f);
                v2 = fmaxf(v2, 0.f); v3 = fmaxf(v3, 0.f);
            }
            if (toHalf) {
                if (r0 < M)
                    *(__half2*)(outBh + (size_t)r0 * 128 + cc) =
                        __floats2half2_rn(v0, v1);
                if (r0 + 8 < M)
                    *(__half2*)(outBh + (size_t)(r0 + 8) * 128 + cc) =
                        __floats2half2_rn(v2, v3);
            } else {
                if (r0 < M)
                    *(float2*)(outA + (size_t)r0 * 128 + cc) = make_float2(v0, v1);
                if (r0 + 8 < M)
                    *(float2*)(outA + (size_t)(r0 + 8) * 128 + cc) = make_float2(v2, v3);
            }
        }
    }
}

// ---------------- TF32 MMA output projection: out = H2 @ Wo + b -------------
#define OAST 132
#define OBST 44
#define OSMEM_F (128 * OAST + 128 * OBST)
#define OSMEM_BYTES (OSMEM_F * 4)

__global__ __launch_bounds__(256, 2)
void out_gemm(const float* __restrict__ H2, const float* __restrict__ Wo,
              const float* __restrict__ bias, float* __restrict__ out, int M) {
    extern __shared__ float smem[];
    float* As = smem;
    float* Bs = smem + 128 * OAST;
    const int tid = threadIdx.x;
    const int bm = blockIdx.x * 128;
    const int lane = tid & 31, wid = tid >> 5;
    const int fr = lane >> 2, fc = lane & 3;

    #pragma unroll
    for (int i = 0; i < 16; i++) {
        int id = tid + 256 * i;
        int arow = id >> 5, c4 = id & 31;
        bool p = (bm + arow) < M;
        cpasync16(As + arow * OAST + c4 * 4,
                  H2 + (size_t)(bm + arow) * 128 + c4 * 4, p);
    }
    #pragma unroll
    for (int i = 0; i < 5; i++) {
        int id = tid + 256 * i;
        int wrow = id / 10, c4 = id % 10;
        cpasync16(Bs + wrow * OBST + c4 * 4,
                  Wo + (size_t)wrow * CLS + c4 * 4, true);
    }
    asm volatile("cp.async.commit_group;" ::: "memory");
    asm volatile("cp.async.wait_group 0;" ::: "memory");
    __syncthreads();

    const int m0 = wid * 16;
    float acc[5][4];
    #pragma unroll
    for (int nt = 0; nt < 5; nt++)
        #pragma unroll
        for (int j = 0; j < 4; j++) acc[nt][j] = 0.f;

    #pragma unroll
    for (int kk = 0; kk < 128; kk += 8) {
        unsigned af[4];
        af[0] = tf32u(As[(m0 + fr)     * OAST + kk + fc]);
        af[1] = tf32u(As[(m0 + fr + 8) * OAST + kk + fc]);
        af[2] = tf32u(As[(m0 + fr)     * OAST + kk + fc + 4]);
        af[3] = tf32u(As[(m0 + fr + 8) * OAST + kk + fc + 4]);
        #pragma unroll
        for (int nt = 0; nt < 5; nt++) {
            int n0 = nt * 8;
            unsigned b0 = __float_as_uint(Bs[(kk + fc)     * OBST + n0 + fr]);
            unsigned b1 = __float_as_uint(Bs[(kk + 4 + fc) * OBST + n0 + fr]);
            mma_tf32(acc[nt], af, b0, b1);
        }
    }

    #pragma unroll
    for (int nt = 0; nt < 5; nt++) {
        int r0 = bm + m0 + fr;
        int cc = nt * 8 + 2 * fc;
        float b0 = bias[cc], b1 = bias[cc + 1];
        if (r0 < M) {
            float2 o = make_float2(acc[nt][0] + b0, acc[nt][1] + b1);
            *(float2*)(out + (size_t)r0 * CLS + cc) = o;
        }
        if (r0 + 8 < M) {
            float2 o = make_float2(acc[nt][2] + b0, acc[nt][3] + b1);
            *(float2*)(out + (size_t)(r0 + 8) * CLS + cc) = o;
        }
    }
}

// ---------------- host side -------------------------------------------------
extern "C" void kernel_launch(void* const* d_in, const int* in_sizes, int n_in,
                              void* d_out, int out_size) {
    const float* x      = (const float*)d_in[0];
    const int*   ei     = (const int*)  d_in[1];
    const float* w1_pre = (const float*)d_in[2];
    const float* b1_pre = (const float*)d_in[3];
    const float* w1_post= (const float*)d_in[4];
    const float* b1_post= (const float*)d_in[5];
    const float* w1_lin = (const float*)d_in[6];
    const float* b1_lin = (const float*)d_in[7];
    const float* w2_pre = (const float*)d_in[8];
    const float* b2_pre = (const float*)d_in[9];
    const float* w2_post= (const float*)d_in[10];
    const float* b2_post= (const float*)d_in[11];
    const float* w2_lin = (const float*)d_in[12];
    const float* b2_lin = (const float*)d_in[13];
    const float* w_out  = (const float*)d_in[14];
    const float* b_out  = (const float*)d_in[15];
    float* out = (float*)d_out;

    static int init_done = 0;
    if (!init_done) {
        cudaFuncSetAttribute(mma_gemm, cudaFuncAttributeMaxDynamicSharedMemorySize,
                             GSMEM_BYTES);
        cudaFuncSetAttribute(out_gemm, cudaFuncAttributeMaxDynamicSharedMemorySize,
                             OSMEM_BYTES);
        init_done = 1;
    }

    void *pA, *pBh, *pH, *pH2, *pS, *pM, *pIC, *pWpreH, *pWfT1, *pWfT2,
         *pWfb1, *pWfb2, *pWoR, *pHist, *pCur;
    cudaGetSymbolAddress(&pA, g_A);
    cudaGetSymbolAddress(&pBh, g_Bh);
    cudaGetSymbolAddress(&pH, g_H);
    cudaGetSymbolAddress(&pH2, g_H2);
    cudaGetSymbolAddress(&pS, g_S);
    cudaGetSymbolAddress(&pM, g_M);
    cudaGetSymbolAddress(&pIC, g_IC);
    cudaGetSymbolAddress(&pWpreH, g_WpreH);
    cudaGetSymbolAddress(&pWfT1, g_WfT1);
    cudaGetSymbolAddress(&pWfT2, g_WfT2);
    cudaGetSymbolAddress(&pWfb1, g_Wfb1);
    cudaGetSymbolAddress(&pWfb2, g_Wfb2);
    cudaGetSymbolAddress(&pWoR, g_WoR);
    cudaGetSymbolAddress(&pHist, g_hist);
    cudaGetSymbolAddress(&pCur, g_cur);

    const int* srcp = ei;           // edge_index[0]
    const int* dstp = ei + NEDGES;  // edge_index[1]

    // ---- graph preprocessing (single stream) --------------------------------
    cudaMemsetAsync(pHist, 0, NNODES * sizeof(int));
    cudaMemsetAsync(pCur,  0, NNODES * sizeof(int));
    hist_kernel<<<(NEDGES + 255) / 256, 256>>>(dstp);
    scan_kernel<<<1, 1024>>>();
    scatter_kernel<<<(NEDGES + 255) / 256, 256>>>(srcp, dstp);

    // ---- weight preprocessing ----------------------------------------------
    prep_weights<<<(PREP_W + PREP_O + 255) / 256, 256>>>(w1_pre, w2_pre, w_out);
    fuse_kernel<<<65, 128>>>(w1_post, b1_post, w1_lin, b1_lin,
                             (__half*)pWfT1, (float*)pWfb1);
    fuse_kernel<<<65, 128>>>(w2_post, b2_post, w2_lin, b2_lin,
                             (__half*)pWfT2, (float*)pWfb2);

    const int MB = (NNODES + 127) / 128;

    // ---- layer 1 -----------------------------------------------------------
    GemmSrcs pre1; pre1.s[0] = x; pre1.s[1] = x; pre1.s[2] = x; pre1.s[3] = x;
    mma_gemm<<<dim3(2, MB), 256, GSMEM_BYTES>>>(
        pre1, (const __half*)pWpreH, b1_pre, (float*)pA, (__half*)pBh,
        nullptr, -1, NNODES, 128 / 32, 0, 128);
    aggregate_kernel<<<(NNODES + 7) / 8, 256>>>();

    GemmSrcs cat1; cat1.s[0] = x; cat1.s[1] = (const float*)pS;
    cat1.s[2] = (const float*)pM; cat1.s[3] = (const float*)pS;
    mma_gemm<<<dim3(1, MB), 256, GSMEM_BYTES>>>(
        cat1, (const __half*)pWfT1, (const float*)pWfb1,
        (float*)pH, (__half*)nullptr, (const float*)pIC, 1, NNODES, 512 / 32, 1, 512);

    // ---- layer 2 -----------------------------------------------------------
    GemmSrcs pre2; pre2.s[0] = (const float*)pH; pre2.s[1] = pre2.s[0];
    pre2.s[2] = pre2.s[0]; pre2.s[3] = pre2.s[0];
    mma_gemm<<<dim3(2, MB), 256, GSMEM_BYTES>>>(
        pre2, (const __half*)pWpreH + 2 * 128 * 128, b2_pre, (float*)pA, (__half*)pBh,
        nullptr, -1, NNODES, 128 / 32, 0, 128);
    aggregate_kernel<<<(NNODES + 7) / 8, 256>>>();

    GemmSrcs cat2; cat2.s[0] = (const float*)pH; cat2.s[1] = (const float*)pS;
    cat2.s[2] = (const float*)pM; cat2.s[3] = (const float*)pS;
    mma_gemm<<<dim3(1, MB), 256, GSMEM_BYTES>>>(
        cat2, (const __half*)pWfT2, (const float*)pWfb2,
        (float*)pH2, (__half*)nullptr, (const float*)pIC, 1, NNODES, 512 / 32, 1, 512);

    // ---- output projection (TF32 MMA) --------------------------------------
    out_gemm<<<(NNODES + 127) / 128, 256, OSMEM_BYTES>>>(
        (const float*)pH2, (const float*)pWoR, b_out, out, NNODES);
}

// round 13
// speedup vs baseline: 1.0990x; 1.0990x over previous
#include <cuda_runtime.h>
#include <cuda_fp16.h>
#include <math.h>
#include <stdint.h>

#define NNODES 50000
#define NEDGES 500000
#define FDIM   128
#define CLS    40

// ---------------- scratch (static device globals; no allocation) ------------
__device__ __half g_Xh  [NNODES * FDIM];   // fp16 copy of x
__device__ float  g_A   [NNODES * FDIM];   // A' = x @ W_top + b_pre (fp32)
__device__ __half g_Bh  [NNODES * FDIM];   // B  = x @ W_bot        (fp16)
__device__ __half g_Sh  [NNODES * FDIM];   // SUM aggregator  (fp16)
__device__ __half g_Mh  [NNODES * FDIM];   // MAX aggregator  (fp16)
__device__ __half g_Hh  [NNODES * FDIM];   // hidden after layer 1 (fp16)
__device__ __half g_H2h [NNODES * FDIM];   // hidden after layer 2 (fp16)
__device__ float  g_IC  [NNODES + 128];    // 1/max(cnt,1) per node (padded)
__device__ __half g_WpreH[2 * 2 * FDIM * FDIM]; // [layer][half][n][k] fp16 transposed
__device__ __half g_WfT1[FDIM * 512];      // fused W' layer 1, [n][k] fp16 transposed
__device__ __half g_WfT2[FDIM * 512];      // fused W' layer 2, [n][k] fp16 transposed
__device__ float  g_Wfb1[FDIM];            // fused bias layer 1 (fp32)
__device__ float  g_Wfb2[FDIM];            // fused bias layer 2 (fp32)
__device__ __half g_WoTh[CLS * FDIM];      // w_out transposed [n][k] fp16
__device__ int    g_hist[NNODES];
__device__ int    g_off [NNODES + 1];
__device__ int    g_cur [NNODES];
__device__ int    g_ssrc[NEDGES];          // src ids grouped (counting-sorted) by dst

// ---------------- helpers ---------------------------------------------------
__device__ __forceinline__ unsigned pack_h2(float lo, float hi) {
    __half2 h = __floats2half2_rn(lo, hi);   // .x = lo (low 16 bits) = lower k
    return *reinterpret_cast<unsigned*>(&h);
}

__device__ __forceinline__ void cpasync16(void* dst, const void* src, bool pred) {
    unsigned sa = (unsigned)__cvta_generic_to_shared(dst);
    int sz = pred ? 16 : 0;
    asm volatile("cp.async.cg.shared.global [%0], [%1], 16, %2;\n"
                 :: "r"(sa), "l"(src), "r"(sz));
}

// fp16 MMA, fp32 accumulate: D(16x8) += A(16x16) * B(16x8)
__device__ __forceinline__ void mma_f16(float* c, const unsigned* a,
                                        unsigned b0, unsigned b1) {
    asm volatile(
        "mma.sync.aligned.m16n8k16.row.col.f32.f16.f16.f32 "
        "{%0,%1,%2,%3}, {%4,%5,%6,%7}, {%8,%9}, {%0,%1,%2,%3};"
        : "+f"(c[0]), "+f"(c[1]), "+f"(c[2]), "+f"(c[3])
        : "r"(a[0]), "r"(a[1]), "r"(a[2]), "r"(a[3]), "r"(b0), "r"(b1));
}

// ---------------- graph preprocessing ---------------------------------------
__global__ void hist_kernel(const int* __restrict__ dst) {
    int i = blockIdx.x * blockDim.x + threadIdx.x;
    if (i < NEDGES) atomicAdd(&g_hist[dst[i]], 1);
}

__global__ void scan_kernel() {  // 1 block, 1024 threads
    __shared__ int s[1024];
    const int t = threadIdx.x;
    const int chunk = (NNODES + 1023) / 1024;
    int beg = t * chunk;
    int end = beg + chunk; if (end > NNODES) end = NNODES;
    int sum = 0;
    for (int i = beg; i < end; i++) sum += g_hist[i];
    s[t] = sum;
    __syncthreads();
    for (int d = 1; d < 1024; d <<= 1) {
        int v = (t >= d) ? s[t - d] : 0;
        __syncthreads();
        s[t] += v;
        __syncthreads();
    }
    int run = (t > 0) ? s[t - 1] : 0;
    for (int i = beg; i < end; i++) { g_off[i] = run; run += g_hist[i]; }
    if (t == 0) g_off[NNODES] = NEDGES;
}

__global__ void scatter_kernel(const int* __restrict__ src, const int* __restrict__ dst) {
    int i = blockIdx.x * blockDim.x + threadIdx.x;
    if (i >= NEDGES) return;
    int d = dst[i];
    int p = g_off[d] + atomicAdd(&g_cur[d], 1);
    g_ssrc[p] = src[i];
}

// ---------------- input conversion x -> fp16 (vectorized) --------------------
__global__ void cvt_x_kernel(const float* __restrict__ x) {
    int i = blockIdx.x * blockDim.x + threadIdx.x;
    if (i < NNODES * FDIM / 4) {
        float4 v = __ldg(&((const float4*)x)[i]);
        uint2 o;
        o.x = pack_h2(v.x, v.y);
        o.y = pack_h2(v.z, v.w);
        ((uint2*)g_Xh)[i] = o;
    }
}

// ---------------- weight preprocessing ---------------------------------------
// g_WpreH[((l*2+h)*128 + n)*128 + k] = fp16( w_pre_l[(h*128+k)*128 + n] )
// g_WoTh[n*128 + k] = fp16( w_out[k*CLS + n] )
#define PREP_W  (2 * 2 * FDIM * FDIM)           // 65536
#define PREP_O  (CLS * FDIM)                    // 5120
__global__ void prep_weights(const float* __restrict__ w1,
                             const float* __restrict__ w2,
                             const float* __restrict__ wo) {
    int i = blockIdx.x * blockDim.x + threadIdx.x;
    if (i < PREP_W) {
        int k = i & 127;
        int n = (i >> 7) & 127;
        int h = (i >> 14) & 1;
        int l = i >> 15;
        const float* w = l ? w2 : w1;
        g_WpreH[i] = __float2half_rn(__ldg(&w[(h * 128 + k) * 128 + n]));
    } else if (i < PREP_W + PREP_O) {
        int j = i - PREP_W;
        int n = j >> 7, k = j & 127;
        g_WoTh[j] = __float2half_rn(__ldg(&wo[k * CLS + n]));
    }
}

// ---------------- aggregation (warp/node, fp16 gather + fp16 stores) ----------
// B rows fp16 (256B): one LDG.64 per lane per edge. fp32 accumulate.
// S = cnt*A'(fp32) + sumB -> fp16 ; M = cnt>0 ? A'+maxB : 0 -> fp16.
__global__ void aggregate_kernel() {
    int node = (blockIdx.x * blockDim.x + threadIdx.x) >> 5;
    if (node >= NNODES) return;
    int lane = threadIdx.x & 31;
    int beg = g_off[node], end = g_off[node + 1];
    const uint2* Bv = (const uint2*)g_Bh;        // 32 uint2 (8B) per row
    float4 s = make_float4(0.f, 0.f, 0.f, 0.f);
    float4 m = make_float4(-3.4e38f, -3.4e38f, -3.4e38f, -3.4e38f);
    int e = beg;
    for (; e + 3 < end; e += 4) {
        int sv0 = __ldg(&g_ssrc[e]);
        int sv1 = __ldg(&g_ssrc[e + 1]);
        int sv2 = __ldg(&g_ssrc[e + 2]);
        int sv3 = __ldg(&g_ssrc[e + 3]);
        uint2 r0 = __ldg(&Bv[(size_t)sv0 * 32 + lane]);
        uint2 r1 = __ldg(&Bv[(size_t)sv1 * 32 + lane]);
        uint2 r2 = __ldg(&Bv[(size_t)sv2 * 32 + lane]);
        uint2 r3 = __ldg(&Bv[(size_t)sv3 * 32 + lane]);
        float2 a0 = __half22float2(*(__half2*)&r0.x);
        float2 b0 = __half22float2(*(__half2*)&r0.y);
        float2 a1 = __half22float2(*(__half2*)&r1.x);
        float2 b1 = __half22float2(*(__half2*)&r1.y);
        float2 a2 = __half22float2(*(__half2*)&r2.x);
        float2 b2 = __half22float2(*(__half2*)&r2.y);
        float2 a3 = __half22float2(*(__half2*)&r3.x);
        float2 b3 = __half22float2(*(__half2*)&r3.y);
        s.x += (a0.x + a1.x) + (a2.x + a3.x);
        s.y += (a0.y + a1.y) + (a2.y + a3.y);
        s.z += (b0.x + b1.x) + (b2.x + b3.x);
        s.w += (b0.y + b1.y) + (b2.y + b3.y);
        m.x = fmaxf(m.x, fmaxf(fmaxf(a0.x, a1.x), fmaxf(a2.x, a3.x)));
        m.y = fmaxf(m.y, fmaxf(fmaxf(a0.y, a1.y), fmaxf(a2.y, a3.y)));
        m.z = fmaxf(m.z, fmaxf(fmaxf(b0.x, b1.x), fmaxf(b2.x, b3.x)));
        m.w = fmaxf(m.w, fmaxf(fmaxf(b0.y, b1.y), fmaxf(b2.y, b3.y)));
    }
    for (; e < end; e++) {
        int sv = __ldg(&g_ssrc[e]);
        uint2 r = __ldg(&Bv[(size_t)sv * 32 + lane]);
        float2 a = __half22float2(*(__half2*)&r.x);
        float2 b = __half22float2(*(__half2*)&r.y);
        s.x += a.x; s.y += a.y; s.z += b.x; s.w += b.y;
        m.x = fmaxf(m.x, a.x); m.y = fmaxf(m.y, a.y);
        m.z = fmaxf(m.z, b.x); m.w = fmaxf(m.w, b.y);
    }
    size_t o = (size_t)node * 32 + lane;   // cols 4*lane..4*lane+3
    float c = (float)(end - beg);
    float ic = 1.f / fmaxf(c, 1.f);
    if (lane == 0) g_IC[node] = ic;
    float4 a = ((const float4*)g_A)[o];
    float tx = fmaf(c, a.x, s.x), ty = fmaf(c, a.y, s.y);
    float tz = fmaf(c, a.z, s.z), tw = fmaf(c, a.w, s.w);
    uint2 sv2o;
    sv2o.x = pack_h2(tx, ty); sv2o.y = pack_h2(tz, tw);
    ((uint2*)g_Sh)[o] = sv2o;
    bool nz = (c > 0.f);
    float mx = nz ? (a.x + m.x) : 0.f, my = nz ? (a.y + m.y) : 0.f;
    float mz = nz ? (a.z + m.z) : 0.f, mw = nz ? (a.w + m.w) : 0.f;
    uint2 mv2o;
    mv2o.x = pack_h2(mx, my); mv2o.y = pack_h2(mz, mw);
    ((uint2*)g_Mh)[o] = mv2o;
}

// ---------------- fused post@lin weight: tiled, transposed fp16 output -------
__global__ void fuse_kernel(const float* __restrict__ wpost, const float* __restrict__ bpost,
                            const float* __restrict__ wlin,  const float* __restrict__ blin,
                            __half* __restrict__ wfT, float* __restrict__ wfb) {
    __shared__ float srow[8][FDIM];
    const int b = blockIdx.x, c = threadIdx.x;   // 128 threads
    if (b < 64) {
        #pragma unroll
        for (int j = 0; j < 8; j++)
            srow[j][c] = wpost[(size_t)(8 * b + j) * FDIM + c];
        __syncthreads();
        float acc[8] = {};
        #pragma unroll 4
        for (int k = 0; k < FDIM; k++) {
            float wl = wlin[k * FDIM + c];
            #pragma unroll
            for (int j = 0; j < 8; j++) acc[j] = fmaf(srow[j][k], wl, acc[j]);
        }
        #pragma unroll
        for (int j = 0; j < 8; j++)
            wfT[(size_t)c * 512 + 8 * b + j] = __float2half_rn(acc[j]);
    } else {
        srow[0][c] = bpost[c];
        __syncthreads();
        float acc = blin[c];
        #pragma unroll 4
        for (int k = 0; k < FDIM; k++) acc = fmaf(srow[0][k], wlin[k * FDIM + c], acc);
        wfb[c] = acc;
    }
}

// ---------------- fp16 tensor-core GEMM (fp16 A smem) ------------------------
// Block 128(M) x 128(N), K-slab 32, 2-stage cp.async. 8 warps 4(M)x2(N).
// A: fp16 gmem -> fp16 smem -> direct LDS.32 frags (no cvt in mainloop).
// B: transposed fp16 weights. SCALE unpack/scale/repacks mean-segment frags only.
// Pre mode (gridDim.x==2): x=0 writes fp32 A'+bias; x=1 writes fp16 B.
// Cat mode (gridDim.x==1): writes fp16 H.
#define ASTH 40              // A smem row stride (halves): 32 + 8 pad (80B)
#define BSTH 72              // B smem row stride (halves): 64 + 8 pad (144B)
#define STGH (128 * ASTH + 128 * BSTH)      // halves per stage = 14336
#define GSMEM_BYTES (2 * STGH * 2)          // 57344

struct GemmSrcs { const __half* s[4]; };

template<bool SCALE>
__device__ __forceinline__ void mma_block_h(const __half* __restrict__ Ash,
                                            const __half* __restrict__ Bsh,
                                            float (*acc)[8][4],
                                            int wm, int wn, int fr, int fc,
                                            const float* fs) {
    #pragma unroll
    for (int ks = 0; ks < 32; ks += 16) {
        unsigned a[2][4];
        #pragma unroll
        for (int mt = 0; mt < 2; mt++) {
            int r0 = wm + mt * 16 + fr;
            unsigned u0 = *(const unsigned*)&Ash[(r0)     * ASTH + ks + 2 * fc];
            unsigned u1 = *(const unsigned*)&Ash[(r0 + 8) * ASTH + ks + 2 * fc];
            unsigned u2 = *(const unsigned*)&Ash[(r0)     * ASTH + ks + 2 * fc + 8];
            unsigned u3 = *(const unsigned*)&Ash[(r0 + 8) * ASTH + ks + 2 * fc + 8];
            if (SCALE) {
                float f0 = fs[mt * 2], f1 = fs[mt * 2 + 1];
                float2 p0 = __half22float2(*(__half2*)&u0);
                float2 p1 = __half22float2(*(__half2*)&u1);
                float2 p2 = __half22float2(*(__half2*)&u2);
                float2 p3 = __half22float2(*(__half2*)&u3);
                u0 = pack_h2(p0.x * f0, p0.y * f0);
                u1 = pack_h2(p1.x * f1, p1.y * f1);
                u2 = pack_h2(p2.x * f0, p2.y * f0);
                u3 = pack_h2(p3.x * f1, p3.y * f1);
            }
            a[mt][0] = u0; a[mt][1] = u1; a[mt][2] = u2; a[mt][3] = u3;
        }
        #pragma unroll
        for (int nt = 0; nt < 8; nt++) {
            int n = wn + nt * 8 + fr;
            unsigned b0 = *(const unsigned*)&Bsh[n * BSTH + ks + 2 * fc];
            unsigned b1 = *(const unsigned*)&Bsh[n * BSTH + ks + 2 * fc + 8];
            mma_f16(acc[0][nt], a[0], b0, b1);
            mma_f16(acc[1][nt], a[1], b0, b1);
        }
    }
}

__global__ __launch_bounds__(256, 2)
void mma_gemm(GemmSrcs srcs, const __half* __restrict__ W,
              const float* __restrict__ bias0,
              float* outA, __half* outBh,
              const float* __restrict__ icvec, int meanSeg,
              int M, int nIter, int relu, int ldB) {
    extern __shared__ __half smemh[];
    const int tid = threadIdx.x;
    const int bm = blockIdx.y * 128;

    const __half* Wb = W;
    const float* bias = bias0;
    bool toHalf = (gridDim.x == 1);             // cat mode writes fp16
    if (gridDim.x == 2 && blockIdx.x == 1) {
        Wb = W + 128 * 128;                     // second weight half
        bias = nullptr;
        toHalf = true;                          // pre mode: B output fp16
    }

    const int lane = tid & 31, wid = tid >> 5;
    const int wm = (wid >> 1) * 32, wn = (wid & 1) * 64;
    const int fr = lane >> 2, fc = lane & 3;

    float fs[4] = {1.f, 1.f, 1.f, 1.f};
    if (icvec) {
        int r = bm + wm + fr;
        fs[0] = icvec[r];      fs[1] = icvec[r + 8];
        fs[2] = icvec[r + 16]; fs[3] = icvec[r + 24];
    }

    float acc[2][8][4];
    #pragma unroll
    for (int mt = 0; mt < 2; mt++)
        #pragma unroll
        for (int nt = 0; nt < 8; nt++)
            #pragma unroll
            for (int j = 0; j < 4; j++) acc[mt][nt][j] = 0.f;

    auto loadStage = [&](int it, int stage) {
        int k0 = it * 32;
        const __half* sp = srcs.s[(k0 >> 7) & 3];
        int kloc = k0 & 127;
        __half* Ash = smemh + stage * STGH;
        __half* Bsh = Ash + 128 * ASTH;
        // A: 128 rows x 32 halves = 4 x 16B chunks/row -> 512 chunks, 2 iters
        #pragma unroll
        for (int i = 0; i < 2; i++) {
            int id = tid + 256 * i;
            int arow = id >> 2, c4 = id & 3;
            bool p = (bm + arow) < M;
            cpasync16(Ash + arow * ASTH + c4 * 8,
                      sp + (size_t)(bm + arow) * 128 + kloc + c4 * 8, p);
        }
        // B: 128 n-rows x 32 halves = 4 chunks/row -> 512 chunks, 2 iters
        #pragma unroll
        for (int i = 0; i < 2; i++) {
            int id = tid + 256 * i;
            int n = id >> 2, c4 = id & 3;
            cpasync16(Bsh + n * BSTH + c4 * 8,
                      Wb + (size_t)n * ldB + k0 + c4 * 8, true);
        }
        asm volatile("cp.async.commit_group;" ::: "memory");
    };

    loadStage(0, 0);
    for (int it = 0; it < nIter; ++it) {
        int cur = it & 1;
        if (it + 1 < nIter) {
            loadStage(it + 1, cur ^ 1);
            asm volatile("cp.async.wait_group 1;" ::: "memory");
        } else {
            asm volatile("cp.async.wait_group 0;" ::: "memory");
        }
        __syncthreads();

        const __half* Ash = smemh + cur * STGH;
        const __half* Bsh = Ash + 128 * ASTH;
        bool ms = (((it * 32) >> 7) == meanSeg);
        if (ms) mma_block_h<true >(Ash, Bsh, acc, wm, wn, fr, fc, fs);
        else    mma_block_h<false>(Ash, Bsh, acc, wm, wn, fr, fc, fs);
        __syncthreads();
    }

    #pragma unroll
    for (int mt = 0; mt < 2; mt++) {
        #pragma unroll
        for (int nt = 0; nt < 8; nt++) {
            int r0 = bm + wm + mt * 16 + fr;
            int cc = wn + nt * 8 + 2 * fc;
            float b0 = 0.f, b1 = 0.f;
            if (bias) { b0 = bias[cc]; b1 = bias[cc + 1]; }
            float v0 = acc[mt][nt][0] + b0, v1 = acc[mt][nt][1] + b1;
            float v2 = acc[mt][nt][2] + b0, v3 = acc[mt][nt][3] + b1;
            if (relu) {
                v0 = fmaxf(v0, 0.f); v1 = fmaxf(v1, 0.f);
                v2 = fmaxf(v2, 0.f); v3 = fmaxf(v3, 0.f);
            }
            if (toHalf) {
                if (r0 < M)
                    *(unsigned*)(outBh + (size_t)r0 * 128 + cc) = pack_h2(v0, v1);
                if (r0 + 8 < M)
                    *(unsigned*)(outBh + (size_t)(r0 + 8) * 128 + cc) = pack_h2(v2, v3);
            } else {
                if (r0 < M)
                    *(float2*)(outA + (size_t)r0 * 128 + cc) = make_float2(v0, v1);
                if (r0 + 8 < M)
                    *(float2*)(outA + (size_t)(r0 + 8) * 128 + cc) = make_float2(v2, v3);
            }
        }
    }
}

// ---------------- fp16 MMA output projection: out = H2h @ WoT^T + b ---------
// One-shot K=128 smem load; 8 warps x 16 rows; N=40 (5 n-subtiles).
#define OASTH 136
#define OBSTH 136
#define OSMEM_BYTES ((128 * OASTH + 40 * OBSTH) * 2)   // 45696

__global__ __launch_bounds__(256, 2)
void out_gemm(const __half* __restrict__ H2h, const __half* __restrict__ WoT,
              const float* __restrict__ bias, float* __restrict__ out, int M) {
    extern __shared__ __half smemh[];
    __half* Ash = smemh;
    __half* Bsh = smemh + 128 * OASTH;
    const int tid = threadIdx.x;
    const int bm = blockIdx.x * 128;
    const int lane = tid & 31, wid = tid >> 5;
    const int fr = lane >> 2, fc = lane & 3;

    // A: 128 rows x 128 halves = 16 chunks/row -> 2048 chunks, 8 iters
    #pragma unroll
    for (int i = 0; i < 8; i++) {
        int id = tid + 256 * i;
        int row = id >> 4, c4 = id & 15;
        bool p = (bm + row) < M;
        cpasync16(Ash + row * OASTH + c4 * 8,
                  H2h + (size_t)(bm + row) * 128 + c4 * 8, p);
    }
    // B: 40 rows x 128 halves = 640 chunks -> 3 iters
    #pragma unroll
    for (int i = 0; i < 3; i++) {
        int id = tid + 256 * i;
        if (id < 40 * 16) {
            int row = id >> 4, c4 = id & 15;
            cpasync16(Bsh + row * OBSTH + c4 * 8,
                      WoT + (size_t)row * 128 + c4 * 8, true);
        }
    }
    asm volatile("cp.async.commit_group;" ::: "memory");
    asm volatile("cp.async.wait_group 0;" ::: "memory");
    __syncthreads();

    const int m0 = wid * 16;
    float acc[5][4];
    #pragma unroll
    for (int nt = 0; nt < 5; nt++)
        #pragma unroll
        for (int j = 0; j < 4; j++) acc[nt][j] = 0.f;

    #pragma unroll
    for (int ks = 0; ks < 128; ks += 16) {
        unsigned a[4];
        a[0] = *(const unsigned*)&Ash[(m0 + fr)     * OASTH + ks + 2 * fc];
        a[1] = *(const unsigned*)&Ash[(m0 + fr + 8) * OASTH + ks + 2 * fc];
        a[2] = *(const unsigned*)&Ash[(m0 + fr)     * OASTH + ks + 2 * fc + 8];
        a[3] = *(const unsigned*)&Ash[(m0 + fr + 8) * OASTH + ks + 2 * fc + 8];
        #pragma unroll
        for (int nt = 0; nt < 5; nt++) {
            int n = nt * 8 + fr;
            unsigned b0 = *(const unsigned*)&Bsh[n * OBSTH + ks + 2 * fc];
            unsigned b1 = *(const unsigned*)&Bsh[n * OBSTH + ks + 2 * fc + 8];
            mma_f16(acc[nt], a, b0, b1);
        }
    }

    #pragma unroll
    for (int nt = 0; nt < 5; nt++) {
        int r0 = bm + m0 + fr;
        int cc = nt * 8 + 2 * fc;
        float b0 = bias[cc], b1 = bias[cc + 1];
        if (r0 < M) {
            float2 o = make_float2(acc[nt][0] + b0, acc[nt][1] + b1);
            *(float2*)(out + (size_t)r0 * CLS + cc) = o;
        }
        if (r0 + 8 < M) {
            float2 o = make_float2(acc[nt][2] + b0, acc[nt][3] + b1);
            *(float2*)(out + (size_t)(r0 + 8) * CLS + cc) = o;
        }
    }
}

// ---------------- host side -------------------------------------------------
extern "C" void kernel_launch(void* const* d_in, const int* in_sizes, int n_in,
                              void* d_out, int out_size) {
    const float* x      = (const float*)d_in[0];
    const int*   ei     = (const int*)  d_in[1];
    const float* w1_pre = (const float*)d_in[2];
    const float* b1_pre = (const float*)d_in[3];
    const float* w1_post= (const float*)d_in[4];
    const float* b1_post= (const float*)d_in[5];
    const float* w1_lin = (const float*)d_in[6];
    const float* b1_lin = (const float*)d_in[7];
    const float* w2_pre = (const float*)d_in[8];
    const float* b2_pre = (const float*)d_in[9];
    const float* w2_post= (const float*)d_in[10];
    const float* b2_post= (const float*)d_in[11];
    const float* w2_lin = (const float*)d_in[12];
    const float* b2_lin = (const float*)d_in[13];
    const float* w_out  = (const float*)d_in[14];
    const float* b_out  = (const float*)d_in[15];
    float* out = (float*)d_out;

    static int init_done = 0;
    if (!init_done) {
        cudaFuncSetAttribute(mma_gemm, cudaFuncAttributeMaxDynamicSharedMemorySize,
                             GSMEM_BYTES);
        cudaFuncSetAttribute(out_gemm, cudaFuncAttributeMaxDynamicSharedMemorySize,
                             OSMEM_BYTES);
        init_done = 1;
    }

    void *pXh, *pA, *pBh, *pSh, *pMh, *pHh, *pH2h, *pIC, *pWpreH,
         *pWfT1, *pWfT2, *pWfb1, *pWfb2, *pWoTh, *pHist, *pCur;
    cudaGetSymbolAddress(&pXh, g_Xh);
    cudaGetSymbolAddress(&pA, g_A);
    cudaGetSymbolAddress(&pBh, g_Bh);
    cudaGetSymbolAddress(&pSh, g_Sh);
    cudaGetSymbolAddress(&pMh, g_Mh);
    cudaGetSymbolAddress(&pHh, g_Hh);
    cudaGetSymbolAddress(&pH2h, g_H2h);
    cudaGetSymbolAddress(&pIC, g_IC);
    cudaGetSymbolAddress(&pWpreH, g_WpreH);
    cudaGetSymbolAddress(&pWfT1, g_WfT1);
    cudaGetSymbolAddress(&pWfT2, g_WfT2);
    cudaGetSymbolAddress(&pWfb1, g_Wfb1);
    cudaGetSymbolAddress(&pWfb2, g_Wfb2);
    cudaGetSymbolAddress(&pWoTh, g_WoTh);
    cudaGetSymbolAddress(&pHist, g_hist);
    cudaGetSymbolAddress(&pCur, g_cur);

    const int* srcp = ei;           // edge_index[0]
    const int* dstp = ei + NEDGES;  // edge_index[1]

    // ---- graph preprocessing (single stream) --------------------------------
    cudaMemsetAsync(pHist, 0, NNODES * sizeof(int));
    cudaMemsetAsync(pCur,  0, NNODES * sizeof(int));
    hist_kernel<<<(NEDGES + 255) / 256, 256>>>(dstp);
    scan_kernel<<<1, 1024>>>();
    scatter_kernel<<<(NEDGES + 255) / 256, 256>>>(srcp, dstp);

    // ---- input + weight preprocessing ---------------------------------------
    cvt_x_kernel<<<(NNODES * FDIM / 4 + 255) / 256, 256>>>(x);
    prep_weights<<<(PREP_W + PREP_O + 255) / 256, 256>>>(w1_pre, w2_pre, w_out);
    fuse_kernel<<<65, 128>>>(w1_post, b1_post, w1_lin, b1_lin,
                             (__half*)pWfT1, (float*)pWfb1);
    fuse_kernel<<<65, 128>>>(w2_post, b2_post, w2_lin, b2_lin,
                             (__half*)pWfT2, (float*)pWfb2);

    const int MB = (NNODES + 127) / 128;

    // ---- layer 1 -----------------------------------------------------------
    GemmSrcs pre1;
    pre1.s[0] = (const __half*)pXh; pre1.s[1] = pre1.s[0];
    pre1.s[2] = pre1.s[0]; pre1.s[3] = pre1.s[0];
    mma_gemm<<<dim3(2, MB), 256, GSMEM_BYTES>>>(
        pre1, (const __half*)pWpreH, b1_pre, (float*)pA, (__half*)pBh,
        nullptr, -1, NNODES, 128 / 32, 0, 128);
    aggregate_kernel<<<(NNODES + 7) / 8, 256>>>();

    GemmSrcs cat1;
    cat1.s[0] = (const __half*)pXh; cat1.s[1] = (const __half*)pSh;
    cat1.s[2] = (const __half*)pMh; cat1.s[3] = (const __half*)pSh;
    mma_gemm<<<dim3(1, MB), 256, GSMEM_BYTES>>>(
        cat1, (const __half*)pWfT1, (const float*)pWfb1,
        (float*)nullptr, (__half*)pHh, (const float*)pIC, 1, NNODES, 512 / 32, 1, 512);

    // ---- layer 2 -----------------------------------------------------------
    GemmSrcs pre2;
    pre2.s[0] = (const __half*)pHh; pre2.s[1] = pre2.s[0];
    pre2.s[2] = pre2.s[0]; pre2.s[3] = pre2.s[0];
    mma_gemm<<<dim3(2, MB), 256, GSMEM_BYTES>>>(
        pre2, (const __half*)pWpreH + 2 * 128 * 128, b2_pre, (float*)pA, (__half*)pBh,
        nullptr, -1, NNODES, 128 / 32, 0, 128);
    aggregate_kernel<<<(NNODES + 7) / 8, 256>>>();

    GemmSrcs cat2;
    cat2.s[0] = (const __half*)pHh; cat2.s[1] = (const __half*)pSh;
    cat2.s[2] = (const __half*)pMh; cat2.s[3] = (const __half*)pSh;
    mma_gemm<<<dim3(1, MB), 256, GSMEM_BYTES>>>(
        cat2, (const __half*)pWfT2, (const float*)pWfb2,
        (float*)nullptr, (__half*)pH2h, (const float*)pIC, 1, NNODES, 512 / 32, 1, 512);

    // ---- output projection (fp16 MMA) ---------------------------------------
    out_gemm<<<(NNODES + 127) / 128, 256, OSMEM_BYTES>>>(
        (const __half*)pH2h, (const __half*)pWoTh, b_out, out, NNODES);
}

// round 14
// speedup vs baseline: 1.3296x; 1.2098x over previous
#include <cuda_runtime.h>
#include <cuda_fp16.h>
#include <math.h>
#include <stdint.h>

#define NNODES 50000
#define NEDGES 500000
#define FDIM   128
#define CLS    40

// ---------------- scratch (static device globals; no allocation) ------------
__device__ __half g_Xh  [NNODES * FDIM];   // fp16 copy of x
__device__ __half g_Ah  [NNODES * FDIM];   // A' = x @ W_top + b_pre (fp16)
__device__ __half g_Bh  [NNODES * FDIM];   // B  = x @ W_bot        (fp16)
__device__ __half g_Sh  [NNODES * FDIM];   // SUM aggregator  (fp16)
__device__ __half g_Mh  [NNODES * FDIM];   // MAX aggregator  (fp16)
__device__ __half g_Hh  [NNODES * FDIM];   // hidden after layer 1 (fp16)
__device__ __half g_H2h [NNODES * FDIM];   // hidden after layer 2 (fp16)
__device__ float  g_IC  [NNODES + 128];    // 1/max(cnt,1) per node (padded)
__device__ __half g_WpreH[2 * 2 * FDIM * FDIM]; // [layer][half][n][k] fp16 transposed
__device__ __half g_WfT1[FDIM * 512];      // fused W' layer 1, [n][k] fp16 transposed
__device__ __half g_WfT2[FDIM * 512];      // fused W' layer 2, [n][k] fp16 transposed
__device__ float  g_Wfb1[FDIM];            // fused bias layer 1 (fp32)
__device__ float  g_Wfb2[FDIM];            // fused bias layer 2 (fp32)
__device__ __half g_WoTh[CLS * FDIM];      // w_out transposed [n][k] fp16
__device__ int    g_hist[NNODES];
__device__ int    g_off [NNODES + 1];
__device__ int    g_cur [NNODES];
__device__ int    g_ssrc[NEDGES];          // src ids grouped (counting-sorted) by dst
#define SCAN_B 196                          // ceil(50000/256)
__device__ int    g_bsum[SCAN_B];
__device__ int    g_boff[SCAN_B];

// ---------------- helpers ---------------------------------------------------
__device__ __forceinline__ unsigned pack_h2(float lo, float hi) {
    __half2 h = __floats2half2_rn(lo, hi);   // .x = lo (low 16 bits) = lower k
    return *reinterpret_cast<unsigned*>(&h);
}

__device__ __forceinline__ void cpasync16(void* dst, const void* src, bool pred) {
    unsigned sa = (unsigned)__cvta_generic_to_shared(dst);
    int sz = pred ? 16 : 0;
    asm volatile("cp.async.cg.shared.global [%0], [%1], 16, %2;\n"
                 :: "r"(sa), "l"(src), "r"(sz));
}

// fp16 MMA, fp32 accumulate: D(16x8) += A(16x16) * B(16x8)
__device__ __forceinline__ void mma_f16(float* c, const unsigned* a,
                                        unsigned b0, unsigned b1) {
    asm volatile(
        "mma.sync.aligned.m16n8k16.row.col.f32.f16.f16.f32 "
        "{%0,%1,%2,%3}, {%4,%5,%6,%7}, {%8,%9}, {%0,%1,%2,%3};"
        : "+f"(c[0]), "+f"(c[1]), "+f"(c[2]), "+f"(c[3])
        : "r"(a[0]), "r"(a[1]), "r"(a[2]), "r"(a[3]), "r"(b0), "r"(b1));
}

// ---------------- graph preprocessing ---------------------------------------
__global__ void hist_kernel(const int* __restrict__ dst) {
    int i = blockIdx.x * blockDim.x + threadIdx.x;
    if (i < NEDGES) atomicAdd(&g_hist[dst[i]], 1);
}

// 3-phase parallel exclusive scan of g_hist -> g_off (coalesced everywhere)
__global__ void scanA_kernel() {   // SCAN_B blocks x 256: block sums
    __shared__ int sh[256];
    int b = blockIdx.x, t = threadIdx.x;
    int i = b * 256 + t;
    sh[t] = (i < NNODES) ? g_hist[i] : 0;
    __syncthreads();
    #pragma unroll
    for (int d = 128; d > 0; d >>= 1) {
        if (t < d) sh[t] += sh[t + d];
        __syncthreads();
    }
    if (t == 0) g_bsum[b] = sh[0];
}

__global__ void scanB_kernel() {   // 1 block x 256: scan of block sums
    __shared__ int sh[256];
    int t = threadIdx.x;
    sh[t] = (t < SCAN_B) ? g_bsum[t] : 0;
    __syncthreads();
    #pragma unroll
    for (int d = 1; d < 256; d <<= 1) {
        int v = (t >= d) ? sh[t - d] : 0;
        __syncthreads();
        sh[t] += v;
        __syncthreads();
    }
    if (t < SCAN_B) g_boff[t] = (t > 0) ? sh[t - 1] : 0;
}

__global__ void scanC_kernel() {   // SCAN_B blocks x 256: final offsets
    __shared__ int sh[256];
    int b = blockIdx.x, t = threadIdx.x;
    int i = b * 256 + t;
    sh[t] = (i < NNODES) ? g_hist[i] : 0;
    __syncthreads();
    #pragma unroll
    for (int d = 1; d < 256; d <<= 1) {
        int v = (t >= d) ? sh[t - d] : 0;
        __syncthreads();
        sh[t] += v;
        __syncthreads();
    }
    int excl = ((t > 0) ? sh[t - 1] : 0) + g_boff[b];
    if (i < NNODES) g_off[i] = excl;
    if (b == 0 && t == 0) g_off[NNODES] = NEDGES;
}

__global__ void scatter_kernel(const int* __restrict__ src, const int* __restrict__ dst) {
    int i = blockIdx.x * blockDim.x + threadIdx.x;
    if (i >= NEDGES) return;
    int d = dst[i];
    int p = g_off[d] + atomicAdd(&g_cur[d], 1);
    g_ssrc[p] = src[i];
}

// ---------------- input conversion x -> fp16 (vectorized) --------------------
__global__ void cvt_x_kernel(const float* __restrict__ x) {
    int i = blockIdx.x * blockDim.x + threadIdx.x;
    if (i < NNODES * FDIM / 4) {
        float4 v = __ldg(&((const float4*)x)[i]);
        uint2 o;
        o.x = pack_h2(v.x, v.y);
        o.y = pack_h2(v.z, v.w);
        ((uint2*)g_Xh)[i] = o;
    }
}

// ---------------- weight preprocessing ---------------------------------------
#define PREP_W  (2 * 2 * FDIM * FDIM)           // 65536
#define PREP_O  (CLS * FDIM)                    // 5120
__global__ void prep_weights(const float* __restrict__ w1,
                             const float* __restrict__ w2,
                             const float* __restrict__ wo) {
    int i = blockIdx.x * blockDim.x + threadIdx.x;
    if (i < PREP_W) {
        int k = i & 127;
        int n = (i >> 7) & 127;
        int h = (i >> 14) & 1;
        int l = i >> 15;
        const float* w = l ? w2 : w1;
        g_WpreH[i] = __float2half_rn(__ldg(&w[(h * 128 + k) * 128 + n]));
    } else if (i < PREP_W + PREP_O) {
        int j = i - PREP_W;
        int n = j >> 7, k = j & 127;
        g_WoTh[j] = __float2half_rn(__ldg(&wo[k * CLS + n]));
    }
}

// ---------------- aggregation (warp/node, fp16 gather, unroll 8) --------------
// B rows fp16 (256B): one LDG.64 per lane per edge, 8 rows in flight.
// fp32 accumulate. A' is fp16. S/M stored fp16.
__global__ void aggregate_kernel() {
    int node = (blockIdx.x * blockDim.x + threadIdx.x) >> 5;
    if (node >= NNODES) return;
    int lane = threadIdx.x & 31;
    int beg = g_off[node], end = g_off[node + 1];
    const uint2* Bv = (const uint2*)g_Bh;        // 32 uint2 (8B) per row
    float4 s = make_float4(0.f, 0.f, 0.f, 0.f);
    float4 m = make_float4(-3.4e38f, -3.4e38f, -3.4e38f, -3.4e38f);
    int e = beg;
    for (; e + 7 < end; e += 8) {
        int sv[8];
        #pragma unroll
        for (int j = 0; j < 8; j++) sv[j] = __ldg(&g_ssrc[e + j]);
        uint2 r[8];
        #pragma unroll
        for (int j = 0; j < 8; j++) r[j] = __ldg(&Bv[(size_t)sv[j] * 32 + lane]);
        #pragma unroll
        for (int j = 0; j < 8; j++) {
            float2 a = __half22float2(*(__half2*)&r[j].x);
            float2 b = __half22float2(*(__half2*)&r[j].y);
            s.x += a.x; s.y += a.y; s.z += b.x; s.w += b.y;
            m.x = fmaxf(m.x, a.x); m.y = fmaxf(m.y, a.y);
            m.z = fmaxf(m.z, b.x); m.w = fmaxf(m.w, b.y);
        }
    }
    for (; e < end; e++) {
        int sv = __ldg(&g_ssrc[e]);
        uint2 r = __ldg(&Bv[(size_t)sv * 32 + lane]);
        float2 a = __half22float2(*(__half2*)&r.x);
        float2 b = __half22float2(*(__half2*)&r.y);
        s.x += a.x; s.y += a.y; s.z += b.x; s.w += b.y;
        m.x = fmaxf(m.x, a.x); m.y = fmaxf(m.y, a.y);
        m.z = fmaxf(m.z, b.x); m.w = fmaxf(m.w, b.y);
    }
    size_t o = (size_t)node * 32 + lane;   // cols 4*lane..4*lane+3
    float c = (float)(end - beg);
    float ic = 1.f / fmaxf(c, 1.f);
    if (lane == 0) g_IC[node] = ic;
    uint2 ar = ((const uint2*)g_Ah)[o];
    float2 a01 = __half22float2(*(__half2*)&ar.x);
    float2 a23 = __half22float2(*(__half2*)&ar.y);
    float tx = fmaf(c, a01.x, s.x), ty = fmaf(c, a01.y, s.y);
    float tz = fmaf(c, a23.x, s.z), tw = fmaf(c, a23.y, s.w);
    uint2 sv2o;
    sv2o.x = pack_h2(tx, ty); sv2o.y = pack_h2(tz, tw);
    ((uint2*)g_Sh)[o] = sv2o;
    bool nz = (c > 0.f);
    float mx = nz ? (a01.x + m.x) : 0.f, my = nz ? (a01.y + m.y) : 0.f;
    float mz = nz ? (a23.x + m.z) : 0.f, mw = nz ? (a23.y + m.w) : 0.f;
    uint2 mv2o;
    mv2o.x = pack_h2(mx, my); mv2o.y = pack_h2(mz, mw);
    ((uint2*)g_Mh)[o] = mv2o;
}

// ---------------- fused post@lin weight: tiled, transposed fp16 output -------
__global__ void fuse_kernel(const float* __restrict__ wpost, const float* __restrict__ bpost,
                            const float* __restrict__ wlin,  const float* __restrict__ blin,
                            __half* __restrict__ wfT, float* __restrict__ wfb) {
    __shared__ float srow[8][FDIM];
    const int b = blockIdx.x, c = threadIdx.x;   // 128 threads
    if (b < 64) {
        #pragma unroll
        for (int j = 0; j < 8; j++)
            srow[j][c] = wpost[(size_t)(8 * b + j) * FDIM + c];
        __syncthreads();
        float acc[8] = {};
        #pragma unroll 4
        for (int k = 0; k < FDIM; k++) {
            float wl = wlin[k * FDIM + c];
            #pragma unroll
            for (int j = 0; j < 8; j++) acc[j] = fmaf(srow[j][k], wl, acc[j]);
        }
        #pragma unroll
        for (int j = 0; j < 8; j++)
            wfT[(size_t)c * 512 + 8 * b + j] = __float2half_rn(acc[j]);
    } else {
        srow[0][c] = bpost[c];
        __syncthreads();
        float acc = blin[c];
        #pragma unroll 4
        for (int k = 0; k < FDIM; k++) acc = fmaf(srow[0][k], wlin[k * FDIM + c], acc);
        wfb[c] = acc;
    }
}

// ---------------- fp16 tensor-core GEMM (fp16 A smem, fp16 outputs) ----------
// Block 128(M) x 128(N), K-slab 32, 2-stage cp.async. 8 warps 4(M)x2(N).
// All outputs fp16. Pre mode (gridDim.x==2): x=0 -> A'(+bias), x=1 -> B.
// Cat mode (gridDim.x==1): -> H (relu). SCALE handles mean segment.
#define ASTH 40              // A smem row stride (halves): 32 + 8 pad (80B)
#define BSTH 72              // B smem row stride (halves): 64 + 8 pad (144B)
#define STGH (128 * ASTH + 128 * BSTH)      // halves per stage = 14336
#define GSMEM_BYTES (2 * STGH * 2)          // 57344

struct GemmSrcs { const __half* s[4]; };

template<bool SCALE>
__device__ __forceinline__ void mma_block_h(const __half* __restrict__ Ash,
                                            const __half* __restrict__ Bsh,
                                            float (*acc)[8][4],
                                            int wm, int wn, int fr, int fc,
                                            const float* fs) {
    #pragma unroll
    for (int ks = 0; ks < 32; ks += 16) {
        unsigned a[2][4];
        #pragma unroll
        for (int mt = 0; mt < 2; mt++) {
            int r0 = wm + mt * 16 + fr;
            unsigned u0 = *(const unsigned*)&Ash[(r0)     * ASTH + ks + 2 * fc];
            unsigned u1 = *(const unsigned*)&Ash[(r0 + 8) * ASTH + ks + 2 * fc];
            unsigned u2 = *(const unsigned*)&Ash[(r0)     * ASTH + ks + 2 * fc + 8];
            unsigned u3 = *(const unsigned*)&Ash[(r0 + 8) * ASTH + ks + 2 * fc + 8];
            if (SCALE) {
                float f0 = fs[mt * 2], f1 = fs[mt * 2 + 1];
                float2 p0 = __half22float2(*(__half2*)&u0);
                float2 p1 = __half22float2(*(__half2*)&u1);
                float2 p2 = __half22float2(*(__half2*)&u2);
                float2 p3 = __half22float2(*(__half2*)&u3);
                u0 = pack_h2(p0.x * f0, p0.y * f0);
                u1 = pack_h2(p1.x * f1, p1.y * f1);
                u2 = pack_h2(p2.x * f0, p2.y * f0);
                u3 = pack_h2(p3.x * f1, p3.y * f1);
            }
            a[mt][0] = u0; a[mt][1] = u1; a[mt][2] = u2; a[mt][3] = u3;
        }
        #pragma unroll
        for (int nt = 0; nt < 8; nt++) {
            int n = wn + nt * 8 + fr;
            unsigned b0 = *(const unsigned*)&Bsh[n * BSTH + ks + 2 * fc];
            unsigned b1 = *(const unsigned*)&Bsh[n * BSTH + ks + 2 * fc + 8];
            mma_f16(acc[0][nt], a[0], b0, b1);
            mma_f16(acc[1][nt], a[1], b0, b1);
        }
    }
}

__global__ __launch_bounds__(256, 2)
void mma_gemm(GemmSrcs srcs, const __half* __restrict__ W,
              const float* __restrict__ bias0,
              __half* outA, __half* outB,
              const float* __restrict__ icvec, int meanSeg,
              int M, int nIter, int relu, int ldB) {
    extern __shared__ __half smemh[];
    const int tid = threadIdx.x;
    const int bm = blockIdx.y * 128;

    const __half* Wb = W;
    const float* bias = bias0;
    __half* out = outA;
    if (gridDim.x == 2 && blockIdx.x == 1) {
        Wb = W + 128 * 128;                     // second weight half
        bias = nullptr;
        out = outB;
    }

    const int lane = tid & 31, wid = tid >> 5;
    const int wm = (wid >> 1) * 32, wn = (wid & 1) * 64;
    const int fr = lane >> 2, fc = lane & 3;

    float fs[4] = {1.f, 1.f, 1.f, 1.f};
    if (icvec) {
        int r = bm + wm + fr;
        fs[0] = icvec[r];      fs[1] = icvec[r + 8];
        fs[2] = icvec[r + 16]; fs[3] = icvec[r + 24];
    }

    float acc[2][8][4];
    #pragma unroll
    for (int mt = 0; mt < 2; mt++)
        #pragma unroll
        for (int nt = 0; nt < 8; nt++)
            #pragma unroll
            for (int j = 0; j < 4; j++) acc[mt][nt][j] = 0.f;

    auto loadStage = [&](int it, int stage) {
        int k0 = it * 32;
        const __half* sp = srcs.s[(k0 >> 7) & 3];
        int kloc = k0 & 127;
        __half* Ash = smemh + stage * STGH;
        __half* Bsh = Ash + 128 * ASTH;
        #pragma unroll
        for (int i = 0; i < 2; i++) {
            int id = tid + 256 * i;
            int arow = id >> 2, c4 = id & 3;
            bool p = (bm + arow) < M;
            cpasync16(Ash + arow * ASTH + c4 * 8,
                      sp + (size_t)(bm + arow) * 128 + kloc + c4 * 8, p);
        }
        #pragma unroll
        for (int i = 0; i < 2; i++) {
            int id = tid + 256 * i;
            int n = id >> 2, c4 = id & 3;
            cpasync16(Bsh + n * BSTH + c4 * 8,
                      Wb + (size_t)n * ldB + k0 + c4 * 8, true);
        }
        asm volatile("cp.async.commit_group;" ::: "memory");
    };

    loadStage(0, 0);
    for (int it = 0; it < nIter; ++it) {
        int cur = it & 1;
        if (it + 1 < nIter) {
            loadStage(it + 1, cur ^ 1);
            asm volatile("cp.async.wait_group 1;" ::: "memory");
        } else {
            asm volatile("cp.async.wait_group 0;" ::: "memory");
        }
        __syncthreads();

        const __half* Ash = smemh + cur * STGH;
        const __half* Bsh = Ash + 128 * ASTH;
        bool ms = (((it * 32) >> 7) == meanSeg);
        if (ms) mma_block_h<true >(Ash, Bsh, acc, wm, wn, fr, fc, fs);
        else    mma_block_h<false>(Ash, Bsh, acc, wm, wn, fr, fc, fs);
        __syncthreads();
    }

    #pragma unroll
    for (int mt = 0; mt < 2; mt++) {
        #pragma unroll
        for (int nt = 0; nt < 8; nt++) {
            int r0 = bm + wm + mt * 16 + fr;
            int cc = wn + nt * 8 + 2 * fc;
            float b0 = 0.f, b1 = 0.f;
            if (bias) { b0 = bias[cc]; b1 = bias[cc + 1]; }
            float v0 = acc[mt][nt][0] + b0, v1 = acc[mt][nt][1] + b1;
            float v2 = acc[mt][nt][2] + b0, v3 = acc[mt][nt][3] + b1;
            if (relu) {
                v0 = fmaxf(v0, 0.f); v1 = fmaxf(v1, 0.f);
                v2 = fmaxf(v2, 0.f); v3 = fmaxf(v3, 0.f);
            }
            if (r0 < M)
                *(unsigned*)(out + (size_t)r0 * 128 + cc) = pack_h2(v0, v1);
            if (r0 + 8 < M)
                *(unsigned*)(out + (size_t)(r0 + 8) * 128 + cc) = pack_h2(v2, v3);
        }
    }
}

// ---------------- fp16 MMA output projection: out = H2h @ WoT^T + b ---------
#define OASTH 136
#define OBSTH 136
#define OSMEM_BYTES ((128 * OASTH + 40 * OBSTH) * 2)   // 45696

__global__ __launch_bounds__(256, 2)
void out_gemm(const __half* __restrict__ H2h, const __half* __restrict__ WoT,
              const float* __restrict__ bias, float* __restrict__ out, int M) {
    extern __shared__ __half smemh[];
    __half* Ash = smemh;
    __half* Bsh = smemh + 128 * OASTH;
    const int tid = threadIdx.x;
    const int bm = blockIdx.x * 128;
    const int lane = tid & 31, wid = tid >> 5;
    const int fr = lane >> 2, fc = lane & 3;

    #pragma unroll
    for (int i = 0; i < 8; i++) {
        int id = tid + 256 * i;
        int row = id >> 4, c4 = id & 15;
        bool p = (bm + row) < M;
        cpasync16(Ash + row * OASTH + c4 * 8,
                  H2h + (size_t)(bm + row) * 128 + c4 * 8, p);
    }
    #pragma unroll
    for (int i = 0; i < 3; i++) {
        int id = tid + 256 * i;
        if (id < 40 * 16) {
            int row = id >> 4, c4 = id & 15;
            cpasync16(Bsh + row * OBSTH + c4 * 8,
                      WoT + (size_t)row * 128 + c4 * 8, true);
        }
    }
    asm volatile("cp.async.commit_group;" ::: "memory");
    asm volatile("cp.async.wait_group 0;" ::: "memory");
    __syncthreads();

    const int m0 = wid * 16;
    float acc[5][4];
    #pragma unroll
    for (int nt = 0; nt < 5; nt++)
        #pragma unroll
        for (int j = 0; j < 4; j++) acc[nt][j] = 0.f;

    #pragma unroll
    for (int ks = 0; ks < 128; ks += 16) {
        unsigned a[4];
        a[0] = *(const unsigned*)&Ash[(m0 + fr)     * OASTH + ks + 2 * fc];
        a[1] = *(const unsigned*)&Ash[(m0 + fr + 8) * OASTH + ks + 2 * fc];
        a[2] = *(const unsigned*)&Ash[(m0 + fr)     * OASTH + ks + 2 * fc + 8];
        a[3] = *(const unsigned*)&Ash[(m0 + fr + 8) * OASTH + ks + 2 * fc + 8];
        #pragma unroll
        for (int nt = 0; nt < 5; nt++) {
            int n = nt * 8 + fr;
            unsigned b0 = *(const unsigned*)&Bsh[n * OBSTH + ks + 2 * fc];
            unsigned b1 = *(const unsigned*)&Bsh[n * OBSTH + ks + 2 * fc + 8];
            mma_f16(acc[nt], a, b0, b1);
        }
    }

    #pragma unroll
    for (int nt = 0; nt < 5; nt++) {
        int r0 = bm + m0 + fr;
        int cc = nt * 8 + 2 * fc;
        float b0 = bias[cc], b1 = bias[cc + 1];
        if (r0 < M) {
            float2 o = make_float2(acc[nt][0] + b0, acc[nt][1] + b1);
            *(float2*)(out + (size_t)r0 * CLS + cc) = o;
        }
        if (r0 + 8 < M) {
            float2 o = make_float2(acc[nt][2] + b0, acc[nt][3] + b1);
            *(float2*)(out + (size_t)(r0 + 8) * CLS + cc) = o;
        }
    }
}

// ---------------- host side -------------------------------------------------
extern "C" void kernel_launch(void* const* d_in, const int* in_sizes, int n_in,
                              void* d_out, int out_size) {
    const float* x      = (const float*)d_in[0];
    const int*   ei     = (const int*)  d_in[1];
    const float* w1_pre = (const float*)d_in[2];
    const float* b1_pre = (const float*)d_in[3];
    const float* w1_post= (const float*)d_in[4];
    const float* b1_post= (const float*)d_in[5];
    const float* w1_lin = (const float*)d_in[6];
    const float* b1_lin = (const float*)d_in[7];
    const float* w2_pre = (const float*)d_in[8];
    const float* b2_pre = (const float*)d_in[9];
    const float* w2_post= (const float*)d_in[10];
    const float* b2_post= (const float*)d_in[11];
    const float* w2_lin = (const float*)d_in[12];
    const float* b2_lin = (const float*)d_in[13];
    const float* w_out  = (const float*)d_in[14];
    const float* b_out  = (const float*)d_in[15];
    float* out = (float*)d_out;

    static int init_done = 0;
    if (!init_done) {
        cudaFuncSetAttribute(mma_gemm, cudaFuncAttributeMaxDynamicSharedMemorySize,
                             GSMEM_BYTES);
        cudaFuncSetAttribute(out_gemm, cudaFuncAttributeMaxDynamicSharedMemorySize,
                             OSMEM_BYTES);
        init_done = 1;
    }

    void *pXh, *pAh, *pBh, *pSh, *pMh, *pHh, *pH2h, *pIC, *pWpreH,
         *pWfT1, *pWfT2, *pWfb1, *pWfb2, *pWoTh, *pHist, *pCur;
    cudaGetSymbolAddress(&pXh, g_Xh);
    cudaGetSymbolAddress(&pAh, g_Ah);
    cudaGetSymbolAddress(&pBh, g_Bh);
    cudaGetSymbolAddress(&pSh, g_Sh);
    cudaGetSymbolAddress(&pMh, g_Mh);
    cudaGetSymbolAddress(&pHh, g_Hh);
    cudaGetSymbolAddress(&pH2h, g_H2h);
    cudaGetSymbolAddress(&pIC, g_IC);
    cudaGetSymbolAddress(&pWpreH, g_WpreH);
    cudaGetSymbolAddress(&pWfT1, g_WfT1);
    cudaGetSymbolAddress(&pWfT2, g_WfT2);
    cudaGetSymbolAddress(&pWfb1, g_Wfb1);
    cudaGetSymbolAddress(&pWfb2, g_Wfb2);
    cudaGetSymbolAddress(&pWoTh, g_WoTh);
    cudaGetSymbolAddress(&pHist, g_hist);
    cudaGetSymbolAddress(&pCur, g_cur);

    const int* srcp = ei;           // edge_index[0]
    const int* dstp = ei + NEDGES;  // edge_index[1]

    // ---- graph preprocessing (single stream) --------------------------------
    cudaMemsetAsync(pHist, 0, NNODES * sizeof(int));
    cudaMemsetAsync(pCur,  0, NNODES * sizeof(int));
    hist_kernel<<<(NEDGES + 255) / 256, 256>>>(dstp);
    scanA_kernel<<<SCAN_B, 256>>>();
    scanB_kernel<<<1, 256>>>();
    scanC_kernel<<<SCAN_B, 256>>>();
    scatter_kernel<<<(NEDGES + 255) / 256, 256>>>(srcp, dstp);

    // ---- input + weight preprocessing ---------------------------------------
    cvt_x_kernel<<<(NNODES * FDIM / 4 + 255) / 256, 256>>>(x);
    prep_weights<<<(PREP_W + PREP_O + 255) / 256, 256>>>(w1_pre, w2_pre, w_out);
    fuse_kernel<<<65, 128>>>(w1_post, b1_post, w1_lin, b1_lin,
                             (__half*)pWfT1, (float*)pWfb1);
    fuse_kernel<<<65, 128>>>(w2_post, b2_post, w2_lin, b2_lin,
                             (__half*)pWfT2, (float*)pWfb2);

    const int MB = (NNODES + 127) / 128;

    // ---- layer 1 -----------------------------------------------------------
    GemmSrcs pre1;
    pre1.s[0] = (const __half*)pXh; pre1.s[1] = pre1.s[0];
    pre1.s[2] = pre1.s[0]; pre1.s[3] = pre1.s[0];
    mma_gemm<<<dim3(2, MB), 256, GSMEM_BYTES>>>(
        pre1, (const __half*)pWpreH, b1_pre, (__half*)pAh, (__half*)pBh,
        nullptr, -1, NNODES, 128 / 32, 0, 128);
    aggregate_kernel<<<(NNODES + 7) / 8, 256>>>();

    GemmSrcs cat1;
    cat1.s[0] = (const __half*)pXh; cat1.s[1] = (const __half*)pSh;
    cat1.s[2] = (const __half*)pMh; cat1.s[3] = (const __half*)pSh;
    mma_gemm<<<dim3(1, MB), 256, GSMEM_BYTES>>>(
        cat1, (const __half*)pWfT1, (const float*)pWfb1,
        (__half*)pHh, (__half*)pHh, (const float*)pIC, 1, NNODES, 512 / 32, 1, 512);

    // ---- layer 2 -----------------------------------------------------------
    GemmSrcs pre2;
    pre2.s[0] = (const __half*)pHh; pre2.s[1] = pre2.s[0];
    pre2.s[2] = pre2.s[0]; pre2.s[3] = pre2.s[0];
    mma_gemm<<<dim3(2, MB), 256, GSMEM_BYTES>>>(
        pre2, (const __half*)pWpreH + 2 * 128 * 128, b2_pre, (__half*)pAh, (__half*)pBh,
        nullptr, -1, NNODES, 128 / 32, 0, 128);
    aggregate_kernel<<<(NNODES + 7) / 8, 256>>>();

    GemmSrcs cat2;
    cat2.s[0] = (const __half*)pHh; cat2.s[1] = (const __half*)pSh;
    cat2.s[2] = (const __half*)pMh; cat2.s[3] = (const __half*)pSh;
    mma_gemm<<<dim3(1, MB), 256, GSMEM_BYTES>>>(
        cat2, (const __half*)pWfT2, (const float*)pWfb2,
        (__half*)pH2h, (__half*)pH2h, (const float*)pIC, 1, NNODES, 512 / 32, 1, 512);

    // ---- output projection (fp16 MMA) ---------------------------------------
    out_gemm<<<(NNODES + 127) / 128, 256, OSMEM_BYTES>>>(
        (const __half*)pH2h, (const __half*)pWoTh, b_out, out, NNODES);
}

// round 15
// speedup vs baseline: 1.4311x; 1.0764x over previous
#include <cuda_runtime.h>
#include <cuda_fp16.h>
#include <math.h>
#include <stdint.h>

#define NNODES 50000
#define NEDGES 500000
#define FDIM   128
#define CLS    40

// ---------------- scratch (static device globals; no allocation) ------------
__device__ __half g_Xh  [NNODES * FDIM];   // fp16 copy of x
__device__ __half g_Ah  [NNODES * FDIM];   // A' = x @ W_top + b_pre (fp16)
__device__ __half g_Bh  [NNODES * FDIM];   // B  = x @ W_bot        (fp16)
__device__ __half g_Sh  [NNODES * FDIM];   // SUM aggregator  (fp16)
__device__ __half g_Mh  [NNODES * FDIM];   // MAX aggregator  (fp16)
__device__ __half g_Hh  [NNODES * FDIM];   // hidden after layer 1 (fp16)
__device__ __half g_H2h [NNODES * FDIM];   // hidden after layer 2 (fp16)
__device__ float  g_IC  [NNODES + 128];    // 1/max(cnt,1) per node (padded)
__device__ __half g_WpreH[2 * 2 * FDIM * FDIM]; // [layer][half][n][k] fp16 transposed
__device__ __half g_WfT1[FDIM * 512];      // fused W' layer 1, [n][k] fp16 transposed
__device__ __half g_WfT2[FDIM * 512];      // fused W' layer 2, [n][k] fp16 transposed
__device__ float  g_Wfb1[FDIM];            // fused bias layer 1 (fp32)
__device__ float  g_Wfb2[FDIM];            // fused bias layer 2 (fp32)
__device__ __half g_WoTh[CLS * FDIM];      // w_out transposed [n][k] fp16
__device__ int    g_hist[NNODES];
__device__ int    g_off [NNODES + 1];
__device__ int    g_cur [NNODES];          // scatter cursor (init = offset)
__device__ int    g_ssrc[NEDGES];          // src ids grouped (counting-sorted) by dst
#define SCAN_B 196                          // ceil(50000/256)
__device__ int    g_bsum[SCAN_B];
__device__ int    g_boff[SCAN_B];

// ---------------- helpers ---------------------------------------------------
__device__ __forceinline__ unsigned pack_h2(float lo, float hi) {
    __half2 h = __floats2half2_rn(lo, hi);   // .x = lo (low 16 bits) = lower k
    return *reinterpret_cast<unsigned*>(&h);
}

__device__ __forceinline__ void cpasync16(void* dst, const void* src, bool pred) {
    unsigned sa = (unsigned)__cvta_generic_to_shared(dst);
    int sz = pred ? 16 : 0;
    asm volatile("cp.async.cg.shared.global [%0], [%1], 16, %2;\n"
                 :: "r"(sa), "l"(src), "r"(sz));
}

// fp16 MMA, fp32 accumulate: D(16x8) += A(16x16) * B(16x8)
__device__ __forceinline__ void mma_f16(float* c, const unsigned* a,
                                        unsigned b0, unsigned b1) {
    asm volatile(
        "mma.sync.aligned.m16n8k16.row.col.f32.f16.f16.f32 "
        "{%0,%1,%2,%3}, {%4,%5,%6,%7}, {%8,%9}, {%0,%1,%2,%3};"
        : "+f"(c[0]), "+f"(c[1]), "+f"(c[2]), "+f"(c[3])
        : "r"(a[0]), "r"(a[1]), "r"(a[2]), "r"(a[3]), "r"(b0), "r"(b1));
}

// ---------------- graph preprocessing ---------------------------------------
__global__ void hist_kernel(const int* __restrict__ dst) {
    int i = blockIdx.x * blockDim.x + threadIdx.x;
    if (i < NEDGES) atomicAdd(&g_hist[dst[i]], 1);
}

// scanA: per-block sums via shuffle reduce (1 sync)
__global__ void scanA_kernel() {
    int b = blockIdx.x, t = threadIdx.x;
    int i = b * 256 + t;
    int v = (i < NNODES) ? g_hist[i] : 0;
    #pragma unroll
    for (int d = 16; d > 0; d >>= 1) v += __shfl_down_sync(0xffffffffu, v, d);
    __shared__ int ws[8];
    if ((t & 31) == 0) ws[t >> 5] = v;
    __syncthreads();
    if (t == 0) {
        int s = 0;
        #pragma unroll
        for (int w = 0; w < 8; w++) s += ws[w];
        g_bsum[b] = s;
    }
}

// scanB: exclusive scan of SCAN_B block sums (shuffle, 2 syncs)
__global__ void scanB_kernel() {
    int t = threadIdx.x;
    int v = (t < SCAN_B) ? g_bsum[t] : 0;
    int lane = t & 31, w = t >> 5;
    int x = v;
    #pragma unroll
    for (int d = 1; d < 32; d <<= 1) {
        int y = __shfl_up_sync(0xffffffffu, x, d);
        if (lane >= d) x += y;
    }
    __shared__ int ws[8];
    if (lane == 31) ws[w] = x;
    __syncthreads();
    if (w == 0) {
        int wv = (lane < 8) ? ws[lane] : 0;
        #pragma unroll
        for (int d = 1; d < 8; d <<= 1) {
            int y = __shfl_up_sync(0xffffffffu, wv, d);
            if (lane >= d) wv += y;
        }
        if (lane < 8) ws[lane] = wv;
    }
    __syncthreads();
    int base = (w > 0) ? ws[w - 1] : 0;
    int incl = base + x;
    if (t < SCAN_B) g_boff[t] = incl - v;   // exclusive
}

// scanC: final offsets; also initializes the scatter cursor (g_cur = offset)
__global__ void scanC_kernel() {
    int b = blockIdx.x, t = threadIdx.x;
    int i = b * 256 + t;
    int v = (i < NNODES) ? g_hist[i] : 0;
    int lane = t & 31, w = t >> 5;
    int x = v;
    #pragma unroll
    for (int d = 1; d < 32; d <<= 1) {
        int y = __shfl_up_sync(0xffffffffu, x, d);
        if (lane >= d) x += y;
    }
    __shared__ int ws[8];
    if (lane == 31) ws[w] = x;
    __syncthreads();
    if (w == 0) {
        int wv = (lane < 8) ? ws[lane] : 0;
        #pragma unroll
        for (int d = 1; d < 8; d <<= 1) {
            int y = __shfl_up_sync(0xffffffffu, wv, d);
            if (lane >= d) wv += y;
        }
        if (lane < 8) ws[lane] = wv;
    }
    __syncthreads();
    int base = ((w > 0) ? ws[w - 1] : 0) + g_boff[b];
    int excl = base + x - v;
    if (i < NNODES) { g_off[i] = excl; g_cur[i] = excl; }
    if (b == 0 && t == 0) g_off[NNODES] = NEDGES;
}

__global__ void scatter_kernel(const int* __restrict__ src, const int* __restrict__ dst) {
    int i = blockIdx.x * blockDim.x + threadIdx.x;
    if (i >= NEDGES) return;
    int p = atomicAdd(&g_cur[dst[i]], 1);   // cursor holds absolute position
    g_ssrc[p] = src[i];
}

// ---------------- input conversion x -> fp16 (vectorized) --------------------
__global__ void cvt_x_kernel(const float* __restrict__ x) {
    int i = blockIdx.x * blockDim.x + threadIdx.x;
    if (i < NNODES * FDIM / 4) {
        float4 v = __ldg(&((const float4*)x)[i]);
        uint2 o;
        o.x = pack_h2(v.x, v.y);
        o.y = pack_h2(v.z, v.w);
        ((uint2*)g_Xh)[i] = o;
    }
}

// ---------------- weight preprocessing ---------------------------------------
#define PREP_W  (2 * 2 * FDIM * FDIM)           // 65536
#define PREP_O  (CLS * FDIM)                    // 5120
__global__ void prep_weights(const float* __restrict__ w1,
                             const float* __restrict__ w2,
                             const float* __restrict__ wo) {
    int i = blockIdx.x * blockDim.x + threadIdx.x;
    if (i < PREP_W) {
        int k = i & 127;
        int n = (i >> 7) & 127;
        int h = (i >> 14) & 1;
        int l = i >> 15;
        const float* w = l ? w2 : w1;
        g_WpreH[i] = __float2half_rn(__ldg(&w[(h * 128 + k) * 128 + n]));
    } else if (i < PREP_W + PREP_O) {
        int j = i - PREP_W;
        int n = j >> 7, k = j & 127;
        g_WoTh[j] = __float2half_rn(__ldg(&wo[k * CLS + n]));
    }
}

// ---------------- aggregation (warp/node, fp16 gather, unroll 8) --------------
__global__ void aggregate_kernel() {
    int node = (blockIdx.x * blockDim.x + threadIdx.x) >> 5;
    if (node >= NNODES) return;
    int lane = threadIdx.x & 31;
    int beg = g_off[node], end = g_off[node + 1];
    const uint2* Bv = (const uint2*)g_Bh;        // 32 uint2 (8B) per row
    float4 s = make_float4(0.f, 0.f, 0.f, 0.f);
    float4 m = make_float4(-3.4e38f, -3.4e38f, -3.4e38f, -3.4e38f);
    int e = beg;
    for (; e + 7 < end; e += 8) {
        int sv[8];
        #pragma unroll
        for (int j = 0; j < 8; j++) sv[j] = __ldg(&g_ssrc[e + j]);
        uint2 r[8];
        #pragma unroll
        for (int j = 0; j < 8; j++) r[j] = __ldg(&Bv[(size_t)sv[j] * 32 + lane]);
        #pragma unroll
        for (int j = 0; j < 8; j++) {
            float2 a = __half22float2(*(__half2*)&r[j].x);
            float2 b = __half22float2(*(__half2*)&r[j].y);
            s.x += a.x; s.y += a.y; s.z += b.x; s.w += b.y;
            m.x = fmaxf(m.x, a.x); m.y = fmaxf(m.y, a.y);
            m.z = fmaxf(m.z, b.x); m.w = fmaxf(m.w, b.y);
        }
    }
    for (; e < end; e++) {
        int sv = __ldg(&g_ssrc[e]);
        uint2 r = __ldg(&Bv[(size_t)sv * 32 + lane]);
        float2 a = __half22float2(*(__half2*)&r.x);
        float2 b = __half22float2(*(__half2*)&r.y);
        s.x += a.x; s.y += a.y; s.z += b.x; s.w += b.y;
        m.x = fmaxf(m.x, a.x); m.y = fmaxf(m.y, a.y);
        m.z = fmaxf(m.z, b.x); m.w = fmaxf(m.w, b.y);
    }
    size_t o = (size_t)node * 32 + lane;   // cols 4*lane..4*lane+3
    float c = (float)(end - beg);
    float ic = 1.f / fmaxf(c, 1.f);
    if (lane == 0) g_IC[node] = ic;
    uint2 ar = ((const uint2*)g_Ah)[o];
    float2 a01 = __half22float2(*(__half2*)&ar.x);
    float2 a23 = __half22float2(*(__half2*)&ar.y);
    float tx = fmaf(c, a01.x, s.x), ty = fmaf(c, a01.y, s.y);
    float tz = fmaf(c, a23.x, s.z), tw = fmaf(c, a23.y, s.w);
    uint2 sv2o;
    sv2o.x = pack_h2(tx, ty); sv2o.y = pack_h2(tz, tw);
    ((uint2*)g_Sh)[o] = sv2o;
    bool nz = (c > 0.f);
    float mx = nz ? (a01.x + m.x) : 0.f, my = nz ? (a01.y + m.y) : 0.f;
    float mz = nz ? (a23.x + m.z) : 0.f, mw = nz ? (a23.y + m.w) : 0.f;
    uint2 mv2o;
    mv2o.x = pack_h2(mx, my); mv2o.y = pack_h2(mz, mw);
    ((uint2*)g_Mh)[o] = mv2o;
}

// ---------------- fused post@lin weight (both layers, one launch) ------------
// blocks 0..64 -> layer 1; blocks 65..129 -> layer 2. Within a layer:
// sub-block 0..63: 8 rows of W' each; sub-block 64: fused bias.
__global__ void fuse_kernel(const float* __restrict__ w1post, const float* __restrict__ b1post,
                            const float* __restrict__ w1lin,  const float* __restrict__ b1lin,
                            const float* __restrict__ w2post, const float* __restrict__ b2post,
                            const float* __restrict__ w2lin,  const float* __restrict__ b2lin,
                            __half* __restrict__ wfT1, float* __restrict__ wfb1,
                            __half* __restrict__ wfT2, float* __restrict__ wfb2) {
    __shared__ float srow[8][FDIM];
    int bb = blockIdx.x;
    int layer = (bb >= 65);
    int b = bb - layer * 65;
    const float* wpost = layer ? w2post : w1post;
    const float* bpost = layer ? b2post : b1post;
    const float* wlin  = layer ? w2lin  : w1lin;
    const float* blin  = layer ? b2lin  : b1lin;
    __half* wfT = layer ? wfT2 : wfT1;
    float* wfb  = layer ? wfb2 : wfb1;
    const int c = threadIdx.x;   // 128 threads
    if (b < 64) {
        #pragma unroll
        for (int j = 0; j < 8; j++)
            srow[j][c] = wpost[(size_t)(8 * b + j) * FDIM + c];
        __syncthreads();
        float acc[8] = {};
        #pragma unroll 4
        for (int k = 0; k < FDIM; k++) {
            float wl = wlin[k * FDIM + c];
            #pragma unroll
            for (int j = 0; j < 8; j++) acc[j] = fmaf(srow[j][k], wl, acc[j]);
        }
        #pragma unroll
        for (int j = 0; j < 8; j++)
            wfT[(size_t)c * 512 + 8 * b + j] = __float2half_rn(acc[j]);
    } else {
        srow[0][c] = bpost[c];
        __syncthreads();
        float acc = blin[c];
        #pragma unroll 4
        for (int k = 0; k < FDIM; k++) acc = fmaf(srow[0][k], wlin[k * FDIM + c], acc);
        wfb[c] = acc;
    }
}

// ---------------- fp16 tensor-core GEMM (3-stage cp.async pipeline) ----------
// Block 128(M) x 128(N), K-slab 32. 8 warps 4(M)x2(N). fp16 in/out.
// Pre mode (gridDim.x==2): x=0 -> A'(+bias), x=1 -> B. Cat mode: -> H (relu).
#define ASTH 40              // A smem row stride (halves): 32 + 8 pad (80B)
#define BSTH 72              // B smem row stride (halves): 64 + 8 pad (144B)
#define STGH (128 * ASTH + 128 * BSTH)      // halves per stage = 14336
#define NSTG 3
#define GSMEM_BYTES (NSTG * STGH * 2)       // 86016

struct GemmSrcs { const __half* s[4]; };

template<bool SCALE>
__device__ __forceinline__ void mma_block_h(const __half* __restrict__ Ash,
                                            const __half* __restrict__ Bsh,
                                            float (*acc)[8][4],
                                            int wm, int wn, int fr, int fc,
                                            const float* fs) {
    #pragma unroll
    for (int ks = 0; ks < 32; ks += 16) {
        unsigned a[2][4];
        #pragma unroll
        for (int mt = 0; mt < 2; mt++) {
            int r0 = wm + mt * 16 + fr;
            unsigned u0 = *(const unsigned*)&Ash[(r0)     * ASTH + ks + 2 * fc];
            unsigned u1 = *(const unsigned*)&Ash[(r0 + 8) * ASTH + ks + 2 * fc];
            unsigned u2 = *(const unsigned*)&Ash[(r0)     * ASTH + ks + 2 * fc + 8];
            unsigned u3 = *(const unsigned*)&Ash[(r0 + 8) * ASTH + ks + 2 * fc + 8];
            if (SCALE) {
                float f0 = fs[mt * 2], f1 = fs[mt * 2 + 1];
                float2 p0 = __half22float2(*(__half2*)&u0);
                float2 p1 = __half22float2(*(__half2*)&u1);
                float2 p2 = __half22float2(*(__half2*)&u2);
                float2 p3 = __half22float2(*(__half2*)&u3);
                u0 = pack_h2(p0.x * f0, p0.y * f0);
                u1 = pack_h2(p1.x * f1, p1.y * f1);
                u2 = pack_h2(p2.x * f0, p2.y * f0);
                u3 = pack_h2(p3.x * f1, p3.y * f1);
            }
            a[mt][0] = u0; a[mt][1] = u1; a[mt][2] = u2; a[mt][3] = u3;
        }
        #pragma unroll
        for (int nt = 0; nt < 8; nt++) {
            int n = wn + nt * 8 + fr;
            unsigned b0 = *(const unsigned*)&Bsh[n * BSTH + ks + 2 * fc];
            unsigned b1 = *(const unsigned*)&Bsh[n * BSTH + ks + 2 * fc + 8];
            mma_f16(acc[0][nt], a[0], b0, b1);
            mma_f16(acc[1][nt], a[1], b0, b1);
        }
    }
}

__global__ __launch_bounds__(256, 2)
void mma_gemm(GemmSrcs srcs, const __half* __restrict__ W,
              const float* __restrict__ bias0,
              __half* outA, __half* outB,
              const float* __restrict__ icvec, int meanSeg,
              int M, int nIter, int relu, int ldB) {
    extern __shared__ __half smemh[];
    const int tid = threadIdx.x;
    const int bm = blockIdx.y * 128;

    const __half* Wb = W;
    const float* bias = bias0;
    __half* out = outA;
    if (gridDim.x == 2 && blockIdx.x == 1) {
        Wb = W + 128 * 128;                     // second weight half
        bias = nullptr;
        out = outB;
    }

    const int lane = tid & 31, wid = tid >> 5;
    const int wm = (wid >> 1) * 32, wn = (wid & 1) * 64;
    const int fr = lane >> 2, fc = lane & 3;

    float fs[4] = {1.f, 1.f, 1.f, 1.f};
    if (icvec) {
        int r = bm + wm + fr;
        fs[0] = icvec[r];      fs[1] = icvec[r + 8];
        fs[2] = icvec[r + 16]; fs[3] = icvec[r + 24];
    }

    float acc[2][8][4];
    #pragma unroll
    for (int mt = 0; mt < 2; mt++)
        #pragma unroll
        for (int nt = 0; nt < 8; nt++)
            #pragma unroll
            for (int j = 0; j < 4; j++) acc[mt][nt][j] = 0.f;

    auto loadStage = [&](int it, int stage) {
        int k0 = it * 32;
        const __half* sp = srcs.s[(k0 >> 7) & 3];
        int kloc = k0 & 127;
        __half* Ash = smemh + stage * STGH;
        __half* Bsh = Ash + 128 * ASTH;
        #pragma unroll
        for (int i = 0; i < 2; i++) {
            int id = tid + 256 * i;
            int arow = id >> 2, c4 = id & 3;
            bool p = (bm + arow) < M;
            cpasync16(Ash + arow * ASTH + c4 * 8,
                      sp + (size_t)(bm + arow) * 128 + kloc + c4 * 8, p);
        }
        #pragma unroll
        for (int i = 0; i < 2; i++) {
            int id = tid + 256 * i;
            int n = id >> 2, c4 = id & 3;
            cpasync16(Bsh + n * BSTH + c4 * 8,
                      Wb + (size_t)n * ldB + k0 + c4 * 8, true);
        }
        asm volatile("cp.async.commit_group;" ::: "memory");
    };

    loadStage(0, 0);
    if (nIter > 1) loadStage(1, 1);
    for (int it = 0; it < nIter; ++it) {
        int cur = it % NSTG;
        if (it + 2 < nIter) {
            loadStage(it + 2, (it + 2) % NSTG);
            asm volatile("cp.async.wait_group 2;" ::: "memory");
        } else if (it + 1 < nIter) {
            asm volatile("cp.async.wait_group 1;" ::: "memory");
        } else {
            asm volatile("cp.async.wait_group 0;" ::: "memory");
        }
        __syncthreads();

        const __half* Ash = smemh + cur * STGH;
        const __half* Bsh = Ash + 128 * ASTH;
        bool ms = (((it * 32) >> 7) == meanSeg);
        if (ms) mma_block_h<true >(Ash, Bsh, acc, wm, wn, fr, fc, fs);
        else    mma_block_h<false>(Ash, Bsh, acc, wm, wn, fr, fc, fs);
        __syncthreads();
    }

    #pragma unroll
    for (int mt = 0; mt < 2; mt++) {
        #pragma unroll
        for (int nt = 0; nt < 8; nt++) {
            int r0 = bm + wm + mt * 16 + fr;
            int cc = wn + nt * 8 + 2 * fc;
            float b0 = 0.f, b1 = 0.f;
            if (bias) { b0 = bias[cc]; b1 = bias[cc + 1]; }
            float v0 = acc[mt][nt][0] + b0, v1 = acc[mt][nt][1] + b1;
            float v2 = acc[mt][nt][2] + b0, v3 = acc[mt][nt][3] + b1;
            if (relu) {
                v0 = fmaxf(v0, 0.f); v1 = fmaxf(v1, 0.f);
                v2 = fmaxf(v2, 0.f); v3 = fmaxf(v3, 0.f);
            }
            if (r0 < M)
                *(unsigned*)(out + (size_t)r0 * 128 + cc) = pack_h2(v0, v1);
            if (r0 + 8 < M)
                *(unsigned*)(out + (size_t)(r0 + 8) * 128 + cc) = pack_h2(v2, v3);
        }
    }
}

// ---------------- fp16 MMA output projection: out = H2h @ WoT^T + b ---------
#define OASTH 136
#define OBSTH 136
#define OSMEM_BYTES ((128 * OASTH + 40 * OBSTH) * 2)   // 45696

__global__ __launch_bounds__(256, 2)
void out_gemm(const __half* __restrict__ H2h, const __half* __restrict__ WoT,
              const float* __restrict__ bias, float* __restrict__ out, int M) {
    extern __shared__ __half smemh[];
    __half* Ash = smemh;
    __half* Bsh = smemh + 128 * OASTH;
    const int tid = threadIdx.x;
    const int bm = blockIdx.x * 128;
    const int lane = tid & 31, wid = tid >> 5;
    const int fr = lane >> 2, fc = lane & 3;

    #pragma unroll
    for (int i = 0; i < 8; i++) {
        int id = tid + 256 * i;
        int row = id >> 4, c4 = id & 15;
        bool p = (bm + row) < M;
        cpasync16(Ash + row * OASTH + c4 * 8,
                  H2h + (size_t)(bm + row) * 128 + c4 * 8, p);
    }
    #pragma unroll
    for (int i = 0; i < 3; i++) {
        int id = tid + 256 * i;
        if (id < 40 * 16) {
            int row = id >> 4, c4 = id & 15;
            cpasync16(Bsh + row * OBSTH + c4 * 8,
                      WoT + (size_t)row * 128 + c4 * 8, true);
        }
    }
    asm volatile("cp.async.commit_group;" ::: "memory");
    asm volatile("cp.async.wait_group 0;" ::: "memory");
    __syncthreads();

    const int m0 = wid * 16;
    float acc[5][4];
    #pragma unroll
    for (int nt = 0; nt < 5; nt++)
        #pragma unroll
        for (int j = 0; j < 4; j++) acc[nt][j] = 0.f;

    #pragma unroll
    for (int ks = 0; ks < 128; ks += 16) {
        unsigned a[4];
        a[0] = *(const unsigned*)&Ash[(m0 + fr)     * OASTH + ks + 2 * fc];
        a[1] = *(const unsigned*)&Ash[(m0 + fr + 8) * OASTH + ks + 2 * fc];
        a[2] = *(const unsigned*)&Ash[(m0 + fr)     * OASTH + ks + 2 * fc + 8];
        a[3] = *(const unsigned*)&Ash[(m0 + fr + 8) * OASTH + ks + 2 * fc + 8];
        #pragma unroll
        for (int nt = 0; nt < 5; nt++) {
            int n = nt * 8 + fr;
            unsigned b0 = *(const unsigned*)&Bsh[n * OBSTH + ks + 2 * fc];
            unsigned b1 = *(const unsigned*)&Bsh[n * OBSTH + ks + 2 * fc + 8];
            mma_f16(acc[nt], a, b0, b1);
        }
    }

    #pragma unroll
    for (int nt = 0; nt < 5; nt++) {
        int r0 = bm + m0 + fr;
        int cc = nt * 8 + 2 * fc;
        float b0 = bias[cc], b1 = bias[cc + 1];
        if (r0 < M) {
            float2 o = make_float2(acc[nt][0] + b0, acc[nt][1] + b1);
            *(float2*)(out + (size_t)r0 * CLS + cc) = o;
        }
        if (r0 + 8 < M) {
            float2 o = make_float2(acc[nt][2] + b0, acc[nt][3] + b1);
            *(float2*)(out + (size_t)(r0 + 8) * CLS + cc) = o;
        }
    }
}

// ---------------- host side -------------------------------------------------
extern "C" void kernel_launch(void* const* d_in, const int* in_sizes, int n_in,
                              void* d_out, int out_size) {
    const float* x      = (const float*)d_in[0];
    const int*   ei     = (const int*)  d_in[1];
    const float* w1_pre = (const float*)d_in[2];
    const float* b1_pre = (const float*)d_in[3];
    const float* w1_post= (const float*)d_in[4];
    const float* b1_post= (const float*)d_in[5];
    const float* w1_lin = (const float*)d_in[6];
    const float* b1_lin = (const float*)d_in[7];
    const float* w2_pre = (const float*)d_in[8];
    const float* b2_pre = (const float*)d_in[9];
    const float* w2_post= (const float*)d_in[10];
    const float* b2_post= (const float*)d_in[11];
    const float* w2_lin = (const float*)d_in[12];
    const float* b2_lin = (const float*)d_in[13];
    const float* w_out  = (const float*)d_in[14];
    const float* b_out  = (const float*)d_in[15];
    float* out = (float*)d_out;

    static int init_done = 0;
    if (!init_done) {
        cudaFuncSetAttribute(mma_gemm, cudaFuncAttributeMaxDynamicSharedMemorySize,
                             GSMEM_BYTES);
        cudaFuncSetAttribute(out_gemm, cudaFuncAttributeMaxDynamicSharedMemorySize,
                             OSMEM_BYTES);
        init_done = 1;
    }

    void *pXh, *pAh, *pBh, *pSh, *pMh, *pHh, *pH2h, *pIC, *pWpreH,
         *pWfT1, *pWfT2, *pWfb1, *pWfb2, *pWoTh, *pHist;
    cudaGetSymbolAddress(&pXh, g_Xh);
    cudaGetSymbolAddress(&pAh, g_Ah);
    cudaGetSymbolAddress(&pBh, g_Bh);
    cudaGetSymbolAddress(&pSh, g_Sh);
    cudaGetSymbolAddress(&pMh, g_Mh);
    cudaGetSymbolAddress(&pHh, g_Hh);
    cudaGetSymbolAddress(&pH2h, g_H2h);
    cudaGetSymbolAddress(&pIC, g_IC);
    cudaGetSymbolAddress(&pWpreH, g_WpreH);
    cudaGetSymbolAddress(&pWfT1, g_WfT1);
    cudaGetSymbolAddress(&pWfT2, g_WfT2);
    cudaGetSymbolAddress(&pWfb1, g_Wfb1);
    cudaGetSymbolAddress(&pWfb2, g_Wfb2);
    cudaGetSymbolAddress(&pWoTh, g_WoTh);
    cudaGetSymbolAddress(&pHist, g_hist);

    const int* srcp = ei;           // edge_index[0]
    const int* dstp = ei + NEDGES;  // edge_index[1]

    // ---- graph preprocessing (single stream) --------------------------------
    cudaMemsetAsync(pHist, 0, NNODES * sizeof(int));
    hist_kernel<<<(NEDGES + 255) / 256, 256>>>(dstp);
    scanA_kernel<<<SCAN_B, 256>>>();
    scanB_kernel<<<1, 256>>>();
    scanC_kernel<<<SCAN_B, 256>>>();
    scatter_kernel<<<(NEDGES + 255) / 256, 256>>>(srcp, dstp);

    // ---- input + weight preprocessing ---------------------------------------
    cvt_x_kernel<<<(NNODES * FDIM / 4 + 255) / 256, 256>>>(x);
    prep_weights<<<(PREP_W + PREP_O + 255) / 256, 256>>>(w1_pre, w2_pre, w_out);
    fuse_kernel<<<130, 128>>>(w1_post, b1_post, w1_lin, b1_lin,
                              w2_post, b2_post, w2_lin, b2_lin,
                              (__half*)pWfT1, (float*)pWfb1,
                              (__half*)pWfT2, (float*)pWfb2);

    const int MB = (NNODES + 127) / 128;

    // ---- layer 1 -----------------------------------------------------------
    GemmSrcs pre1;
    pre1.s[0] = (const __half*)pXh; pre1.s[1] = pre1.s[0];
    pre1.s[2] = pre1.s[0]; pre1.s[3] = pre1.s[0];
    mma_gemm<<<dim3(2, MB), 256, GSMEM_BYTES>>>(
        pre1, (const __half*)pWpreH, b1_pre, (__half*)pAh, (__half*)pBh,
        nullptr, -1, NNODES, 128 / 32, 0, 128);
    aggregate_kernel<<<(NNODES + 7) / 8, 256>>>();

    GemmSrcs cat1;
    cat1.s[0] = (const __half*)pXh; cat1.s[1] = (const __half*)pSh;
    cat1.s[2] = (const __half*)pMh; cat1.s[3] = (const __half*)pSh;
    mma_gemm<<<dim3(1, MB), 256, GSMEM_BYTES>>>(
        cat1, (const __half*)pWfT1, (const float*)pWfb1,
        (__half*)pHh, (__half*)pHh, (const float*)pIC, 1, NNODES, 512 / 32, 1, 512);

    // ---- layer 2 -----------------------------------------------------------
    GemmSrcs pre2;
    pre2.s[0] = (const __half*)pHh; pre2.s[1] = pre2.s[0];
    pre2.s[2] = pre2.s[0]; pre2.s[3] = pre2.s[0];
    mma_gemm<<<dim3(2, MB), 256, GSMEM_BYTES>>>(
        pre2, (const __half*)pWpreH + 2 * 128 * 128, b2_pre, (__half*)pAh, (__half*)pBh,
        nullptr, -1, NNODES, 128 / 32, 0, 128);
    aggregate_kernel<<<(NNODES + 7) / 8, 256>>>();

    GemmSrcs cat2;
    cat2.s[0] = (const __half*)pHh; cat2.s[1] = (const __half*)pSh;
    cat2.s[2] = (const __half*)pMh; cat2.s[3] = (const __half*)pSh;
    mma_gemm<<<dim3(1, MB), 256, GSMEM_BYTES>>>(
        cat2, (const __half*)pWfT2, (const float*)pWfb2,
        (__half*)pH2h, (__half*)pH2h, (const float*)pIC, 1, NNODES, 512 / 32, 1, 512);

    // ---- output projection (fp16 MMA) ---------------------------------------
    out_gemm<<<(NNODES + 127) / 128, 256, OSMEM_BYTES>>>(
        (const __half*)pH2h, (const __half*)pWoTh, b_out, out, NNODES);
}

// round 16
// speedup vs baseline: 1.4452x; 1.0099x over previous
#include <cuda_runtime.h>
#include <cuda_fp16.h>
#include <math.h>
#include <stdint.h>

#define NNODES 50000
#define NEDGES 500000
#define FDIM   128
#define CLS    40

// ---------------- scratch (static device globals; no allocation) ------------
__device__ __half g_Xh  [NNODES * FDIM];   // fp16 copy of x
__device__ __half g_Ah  [NNODES * FDIM];   // A' = x @ W_top + b_pre (fp16)
__device__ __half g_Bh  [NNODES * FDIM];   // B  = x @ W_bot        (fp16)
__device__ __half g_Sh  [NNODES * FDIM];   // SUM aggregator  (fp16)
__device__ __half g_Mh  [NNODES * FDIM];   // MAX aggregator  (fp16)
__device__ __half g_Hh  [NNODES * FDIM];   // hidden after layer 1 (fp16)
__device__ __half g_H2h [NNODES * FDIM];   // hidden after layer 2 (fp16)
__device__ float  g_IC  [NNODES + 128];    // 1/max(cnt,1) per node (padded)
__device__ __half g_WpreH[2 * 2 * FDIM * FDIM]; // [layer][half][n][k] fp16 transposed
__device__ __half g_WfT1[FDIM * 512];      // fused W' layer 1, [n][k] fp16 transposed
__device__ __half g_WfT2[FDIM * 512];      // fused W' layer 2, [n][k] fp16 transposed
__device__ float  g_Wfb1[FDIM];            // fused bias layer 1 (fp32)
__device__ float  g_Wfb2[FDIM];            // fused bias layer 2 (fp32)
__device__ __half g_WoTh[CLS * FDIM];      // w_out transposed [n][k] fp16
__device__ int    g_hist[NNODES];
__device__ int    g_off [NNODES + 1];
__device__ int    g_cur [NNODES];          // scatter cursor (init = offset)
__device__ int    g_ssrc[NEDGES];          // src ids grouped (counting-sorted) by dst
#define SCAN_B 196                          // ceil(50000/256)
__device__ int    g_bsum[SCAN_B];
__device__ int    g_boff[SCAN_B];

// ---------------- helpers ---------------------------------------------------
__device__ __forceinline__ unsigned pack_h2(float lo, float hi) {
    __half2 h = __floats2half2_rn(lo, hi);   // .x = lo (low 16 bits) = lower k
    return *reinterpret_cast<unsigned*>(&h);
}

__device__ __forceinline__ void cpasync16(void* dst, const void* src, bool pred) {
    unsigned sa = (unsigned)__cvta_generic_to_shared(dst);
    int sz = pred ? 16 : 0;
    asm volatile("cp.async.cg.shared.global [%0], [%1], 16, %2;\n"
                 :: "r"(sa), "l"(src), "r"(sz));
}

// fp16 MMA, fp32 accumulate: D(16x8) += A(16x16) * B(16x8)
__device__ __forceinline__ void mma_f16(float* c, const unsigned* a,
                                        unsigned b0, unsigned b1) {
    asm volatile(
        "mma.sync.aligned.m16n8k16.row.col.f32.f16.f16.f32 "
        "{%0,%1,%2,%3}, {%4,%5,%6,%7}, {%8,%9}, {%0,%1,%2,%3};"
        : "+f"(c[0]), "+f"(c[1]), "+f"(c[2]), "+f"(c[3])
        : "r"(a[0]), "r"(a[1]), "r"(a[2]), "r"(a[3]), "r"(b0), "r"(b1));
}

// ---------------- graph preprocessing ---------------------------------------
__global__ void hist_kernel(const int* __restrict__ dst) {
    int i = blockIdx.x * blockDim.x + threadIdx.x;
    if (i < NEDGES) atomicAdd(&g_hist[dst[i]], 1);
}

// scanA: per-block sums via shuffle reduce (1 sync)
__global__ void scanA_kernel() {
    int b = blockIdx.x, t = threadIdx.x;
    int i = b * 256 + t;
    int v = (i < NNODES) ? g_hist[i] : 0;
    #pragma unroll
    for (int d = 16; d > 0; d >>= 1) v += __shfl_down_sync(0xffffffffu, v, d);
    __shared__ int ws[8];
    if ((t & 31) == 0) ws[t >> 5] = v;
    __syncthreads();
    if (t == 0) {
        int s = 0;
        #pragma unroll
        for (int w = 0; w < 8; w++) s += ws[w];
        g_bsum[b] = s;
    }
}

// scanB: exclusive scan of SCAN_B block sums (shuffle, 2 syncs)
__global__ void scanB_kernel() {
    int t = threadIdx.x;
    int v = (t < SCAN_B) ? g_bsum[t] : 0;
    int lane = t & 31, w = t >> 5;
    int x = v;
    #pragma unroll
    for (int d = 1; d < 32; d <<= 1) {
        int y = __shfl_up_sync(0xffffffffu, x, d);
        if (lane >= d) x += y;
    }
    __shared__ int ws[8];
    if (lane == 31) ws[w] = x;
    __syncthreads();
    if (w == 0) {
        int wv = (lane < 8) ? ws[lane] : 0;
        #pragma unroll
        for (int d = 1; d < 8; d <<= 1) {
            int y = __shfl_up_sync(0xffffffffu, wv, d);
            if (lane >= d) wv += y;
        }
        if (lane < 8) ws[lane] = wv;
    }
    __syncthreads();
    int base = (w > 0) ? ws[w - 1] : 0;
    int incl = base + x;
    if (t < SCAN_B) g_boff[t] = incl - v;   // exclusive
}

// scanC: final offsets; also initializes the scatter cursor (g_cur = offset)
__global__ void scanC_kernel() {
    int b = blockIdx.x, t = threadIdx.x;
    int i = b * 256 + t;
    int v = (i < NNODES) ? g_hist[i] : 0;
    int lane = t & 31, w = t >> 5;
    int x = v;
    #pragma unroll
    for (int d = 1; d < 32; d <<= 1) {
        int y = __shfl_up_sync(0xffffffffu, x, d);
        if (lane >= d) x += y;
    }
    __shared__ int ws[8];
    if (lane == 31) ws[w] = x;
    __syncthreads();
    if (w == 0) {
        int wv = (lane < 8) ? ws[lane] : 0;
        #pragma unroll
        for (int d = 1; d < 8; d <<= 1) {
            int y = __shfl_up_sync(0xffffffffu, wv, d);
            if (lane >= d) wv += y;
        }
        if (lane < 8) ws[lane] = wv;
    }
    __syncthreads();
    int base = ((w > 0) ? ws[w - 1] : 0) + g_boff[b];
    int excl = base + x - v;
    if (i < NNODES) { g_off[i] = excl; g_cur[i] = excl; }
    if (b == 0 && t == 0) g_off[NNODES] = NEDGES;
}

__global__ void scatter_kernel(const int* __restrict__ src, const int* __restrict__ dst) {
    int i = blockIdx.x * blockDim.x + threadIdx.x;
    if (i >= NEDGES) return;
    int p = atomicAdd(&g_cur[dst[i]], 1);   // cursor holds absolute position
    g_ssrc[p] = src[i];
}

// ---------------- merged input + weight preprocessing ------------------------
// Range 0: x -> fp16 (uint2 per thread). Range 1: pre-weights transposed fp16.
// Range 2: w_out transposed fp16.
#define CVT_X_N (NNODES * FDIM / 4)             // 1,600,000
#define PREP_W  (2 * 2 * FDIM * FDIM)           // 65536
#define PREP_O  (CLS * FDIM)                    // 5120
#define PREP_TOTAL (CVT_X_N + PREP_W + PREP_O)
__global__ void prep_all(const float* __restrict__ x,
                         const float* __restrict__ w1,
                         const float* __restrict__ w2,
                         const float* __restrict__ wo) {
    int i = blockIdx.x * blockDim.x + threadIdx.x;
    if (i < CVT_X_N) {
        float4 v = __ldg(&((const float4*)x)[i]);
        uint2 o;
        o.x = pack_h2(v.x, v.y);
        o.y = pack_h2(v.z, v.w);
        ((uint2*)g_Xh)[i] = o;
    } else if (i < CVT_X_N + PREP_W) {
        int j = i - CVT_X_N;
        int k = j & 127;
        int n = (j >> 7) & 127;
        int h = (j >> 14) & 1;
        int l = j >> 15;
        const float* w = l ? w2 : w1;
        g_WpreH[j] = __float2half_rn(__ldg(&w[(h * 128 + k) * 128 + n]));
    } else if (i < PREP_TOTAL) {
        int j = i - CVT_X_N - PREP_W;
        int n = j >> 7, k = j & 127;
        g_WoTh[j] = __float2half_rn(__ldg(&wo[k * CLS + n]));
    }
}

// ---------------- aggregation: 2 nodes/warp, uint4 gather, unroll 8 ----------
// Each half-warp (16 lanes) owns one node; lane loads uint4 (8 halves = 16B),
// 16 lanes x 16B = 256B row. Half the LDG count of the uint2 version at the
// same bytes/MLP. Per-column accumulation order unchanged (bit-identical).
__global__ void aggregate_kernel() {
    int gw = (blockIdx.x * blockDim.x + threadIdx.x) >> 5;
    int lane = threadIdx.x & 31;
    int node = gw * 2 + (lane >> 4);
    if (node >= NNODES) return;
    int l16 = lane & 15;
    int beg = g_off[node], end = g_off[node + 1];
    const uint4* Bv = (const uint4*)g_Bh;        // 16 uint4 per row
    float s[8] = {0.f, 0.f, 0.f, 0.f, 0.f, 0.f, 0.f, 0.f};
    float m[8];
    #pragma unroll
    for (int i = 0; i < 8; i++) m[i] = -3.4e38f;
    int e = beg;
    for (; e + 7 < end; e += 8) {
        int sv[8];
        #pragma unroll
        for (int j = 0; j < 8; j++) sv[j] = __ldg(&g_ssrc[e + j]);
        uint4 r[8];
        #pragma unroll
        for (int j = 0; j < 8; j++) r[j] = __ldg(&Bv[(size_t)sv[j] * 16 + l16]);
        #pragma unroll
        for (int j = 0; j < 8; j++) {
            float2 p0 = __half22float2(*(__half2*)&r[j].x);
            float2 p1 = __half22float2(*(__half2*)&r[j].y);
            float2 p2 = __half22float2(*(__half2*)&r[j].z);
            float2 p3 = __half22float2(*(__half2*)&r[j].w);
            s[0] += p0.x; s[1] += p0.y; s[2] += p1.x; s[3] += p1.y;
            s[4] += p2.x; s[5] += p2.y; s[6] += p3.x; s[7] += p3.y;
            m[0] = fmaxf(m[0], p0.x); m[1] = fmaxf(m[1], p0.y);
            m[2] = fmaxf(m[2], p1.x); m[3] = fmaxf(m[3], p1.y);
            m[4] = fmaxf(m[4], p2.x); m[5] = fmaxf(m[5], p2.y);
            m[6] = fmaxf(m[6], p3.x); m[7] = fmaxf(m[7], p3.y);
        }
    }
    for (; e < end; e++) {
        int sv = __ldg(&g_ssrc[e]);
        uint4 r = __ldg(&Bv[(size_t)sv * 16 + l16]);
        float2 p0 = __half22float2(*(__half2*)&r.x);
        float2 p1 = __half22float2(*(__half2*)&r.y);
        float2 p2 = __half22float2(*(__half2*)&r.z);
        float2 p3 = __half22float2(*(__half2*)&r.w);
        s[0] += p0.x; s[1] += p0.y; s[2] += p1.x; s[3] += p1.y;
        s[4] += p2.x; s[5] += p2.y; s[6] += p3.x; s[7] += p3.y;
        m[0] = fmaxf(m[0], p0.x); m[1] = fmaxf(m[1], p0.y);
        m[2] = fmaxf(m[2], p1.x); m[3] = fmaxf(m[3], p1.y);
        m[4] = fmaxf(m[4], p2.x); m[5] = fmaxf(m[5], p2.y);
        m[6] = fmaxf(m[6], p3.x); m[7] = fmaxf(m[7], p3.y);
    }
    size_t o = (size_t)node * 16 + l16;   // uint4 index: cols 8*l16..8*l16+7
    float c = (float)(end - beg);
    float ic = 1.f / fmaxf(c, 1.f);
    if (l16 == 0) g_IC[node] = ic;
    uint4 ar = ((const uint4*)g_Ah)[o];
    float2 a0 = __half22float2(*(__half2*)&ar.x);
    float2 a1 = __half22float2(*(__half2*)&ar.y);
    float2 a2 = __half22float2(*(__half2*)&ar.z);
    float2 a3 = __half22float2(*(__half2*)&ar.w);
    float av[8] = {a0.x, a0.y, a1.x, a1.y, a2.x, a2.y, a3.x, a3.y};
    uint4 so;
    so.x = pack_h2(fmaf(c, av[0], s[0]), fmaf(c, av[1], s[1]));
    so.y = pack_h2(fmaf(c, av[2], s[2]), fmaf(c, av[3], s[3]));
    so.z = pack_h2(fmaf(c, av[4], s[4]), fmaf(c, av[5], s[5]));
    so.w = pack_h2(fmaf(c, av[6], s[6]), fmaf(c, av[7], s[7]));
    ((uint4*)g_Sh)[o] = so;
    bool nz = (c > 0.f);
    uint4 mo;
    mo.x = pack_h2(nz ? (av[0] + m[0]) : 0.f, nz ? (av[1] + m[1]) : 0.f);
    mo.y = pack_h2(nz ? (av[2] + m[2]) : 0.f, nz ? (av[3] + m[3]) : 0.f);
    mo.z = pack_h2(nz ? (av[4] + m[4]) : 0.f, nz ? (av[5] + m[5]) : 0.f);
    mo.w = pack_h2(nz ? (av[6] + m[6]) : 0.f, nz ? (av[7] + m[7]) : 0.f);
    ((uint4*)g_Mh)[o] = mo;
}

// ---------------- fused post@lin weight (both layers, one launch) ------------
__global__ void fuse_kernel(const float* __restrict__ w1post, const float* __restrict__ b1post,
                            const float* __restrict__ w1lin,  const float* __restrict__ b1lin,
                            const float* __restrict__ w2post, const float* __restrict__ b2post,
                            const float* __restrict__ w2lin,  const float* __restrict__ b2lin,
                            __half* __restrict__ wfT1, float* __restrict__ wfb1,
                            __half* __restrict__ wfT2, float* __restrict__ wfb2) {
    __shared__ float srow[8][FDIM];
    int bb = blockIdx.x;
    int layer = (bb >= 65);
    int b = bb - layer * 65;
    const float* wpost = layer ? w2post : w1post;
    const float* bpost = layer ? b2post : b1post;
    const float* wlin  = layer ? w2lin  : w1lin;
    const float* blin  = layer ? b2lin  : b1lin;
    __half* wfT = layer ? wfT2 : wfT1;
    float* wfb  = layer ? wfb2 : wfb1;
    const int c = threadIdx.x;   // 128 threads
    if (b < 64) {
        #pragma unroll
        for (int j = 0; j < 8; j++)
            srow[j][c] = wpost[(size_t)(8 * b + j) * FDIM + c];
        __syncthreads();
        float acc[8] = {};
        #pragma unroll 4
        for (int k = 0; k < FDIM; k++) {
            float wl = wlin[k * FDIM + c];
            #pragma unroll
            for (int j = 0; j < 8; j++) acc[j] = fmaf(srow[j][k], wl, acc[j]);
        }
        #pragma unroll
        for (int j = 0; j < 8; j++)
            wfT[(size_t)c * 512 + 8 * b + j] = __float2half_rn(acc[j]);
    } else {
        srow[0][c] = bpost[c];
        __syncthreads();
        float acc = blin[c];
        #pragma unroll 4
        for (int k = 0; k < FDIM; k++) acc = fmaf(srow[0][k], wlin[k * FDIM + c], acc);
        wfb[c] = acc;
    }
}

// ---------------- fp16 tensor-core GEMM (3-stage cp.async pipeline) ----------
#define ASTH 40              // A smem row stride (halves): 32 + 8 pad (80B)
#define BSTH 72              // B smem row stride (halves): 64 + 8 pad (144B)
#define STGH (128 * ASTH + 128 * BSTH)      // halves per stage = 14336
#define NSTG 3
#define GSMEM_BYTES (NSTG * STGH * 2)       // 86016

struct GemmSrcs { const __half* s[4]; };

template<bool SCALE>
__device__ __forceinline__ void mma_block_h(const __half* __restrict__ Ash,
                                            const __half* __restrict__ Bsh,
                                            float (*acc)[8][4],
                                            int wm, int wn, int fr, int fc,
                                            const float* fs) {
    #pragma unroll
    for (int ks = 0; ks < 32; ks += 16) {
        unsigned a[2][4];
        #pragma unroll
        for (int mt = 0; mt < 2; mt++) {
            int r0 = wm + mt * 16 + fr;
            unsigned u0 = *(const unsigned*)&Ash[(r0)     * ASTH + ks + 2 * fc];
            unsigned u1 = *(const unsigned*)&Ash[(r0 + 8) * ASTH + ks + 2 * fc];
            unsigned u2 = *(const unsigned*)&Ash[(r0)     * ASTH + ks + 2 * fc + 8];
            unsigned u3 = *(const unsigned*)&Ash[(r0 + 8) * ASTH + ks + 2 * fc + 8];
            if (SCALE) {
                float f0 = fs[mt * 2], f1 = fs[mt * 2 + 1];
                float2 p0 = __half22float2(*(__half2*)&u0);
                float2 p1 = __half22float2(*(__half2*)&u1);
                float2 p2 = __half22float2(*(__half2*)&u2);
                float2 p3 = __half22float2(*(__half2*)&u3);
                u0 = pack_h2(p0.x * f0, p0.y * f0);
                u1 = pack_h2(p1.x * f1, p1.y * f1);
                u2 = pack_h2(p2.x * f0, p2.y * f0);
                u3 = pack_h2(p3.x * f1, p3.y * f1);
            }
            a[mt][0] = u0; a[mt][1] = u1; a[mt][2] = u2; a[mt][3] = u3;
        }
        #pragma unroll
        for (int nt = 0; nt < 8; nt++) {
            int n = wn + nt * 8 + fr;
            unsigned b0 = *(const unsigned*)&Bsh[n * BSTH + ks + 2 * fc];
            unsigned b1 = *(const unsigned*)&Bsh[n * BSTH + ks + 2 * fc + 8];
            mma_f16(acc[0][nt], a[0], b0, b1);
            mma_f16(acc[1][nt], a[1], b0, b1);
        }
    }
}

__global__ __launch_bounds__(256, 2)
void mma_gemm(GemmSrcs srcs, const __half* __restrict__ W,
              const float* __restrict__ bias0,
              __half* outA, __half* outB,
              const float* __restrict__ icvec, int meanSeg,
              int M, int nIter, int relu, int ldB) {
    extern __shared__ __half smemh[];
    const int tid = threadIdx.x;
    const int bm = blockIdx.y * 128;

    const __half* Wb = W;
    const float* bias = bias0;
    __half* out = outA;
    if (gridDim.x == 2 && blockIdx.x == 1) {
        Wb = W + 128 * 128;                     // second weight half
        bias = nullptr;
        out = outB;
    }

    const int lane = tid & 31, wid = tid >> 5;
    const int wm = (wid >> 1) * 32, wn = (wid & 1) * 64;
    const int fr = lane >> 2, fc = lane & 3;

    float fs[4] = {1.f, 1.f, 1.f, 1.f};
    if (icvec) {
        int r = bm + wm + fr;
        fs[0] = icvec[r];      fs[1] = icvec[r + 8];
        fs[2] = icvec[r + 16]; fs[3] = icvec[r + 24];
    }

    float acc[2][8][4];
    #pragma unroll
    for (int mt = 0; mt < 2; mt++)
        #pragma unroll
        for (int nt = 0; nt < 8; nt++)
            #pragma unroll
            for (int j = 0; j < 4; j++) acc[mt][nt][j] = 0.f;

    auto loadStage = [&](int it, int stage) {
        int k0 = it * 32;
        const __half* sp = srcs.s[(k0 >> 7) & 3];
        int kloc = k0 & 127;
        __half* Ash = smemh + stage * STGH;
        __half* Bsh = Ash + 128 * ASTH;
        #pragma unroll
        for (int i = 0; i < 2; i++) {
            int id = tid + 256 * i;
            int arow = id >> 2, c4 = id & 3;
            bool p = (bm + arow) < M;
            cpasync16(Ash + arow * ASTH + c4 * 8,
                      sp + (size_t)(bm + arow) * 128 + kloc + c4 * 8, p);
        }
        #pragma unroll
        for (int i = 0; i < 2; i++) {
            int id = tid + 256 * i;
            int n = id >> 2, c4 = id & 3;
            cpasync16(Bsh + n * BSTH + c4 * 8,
                      Wb + (size_t)n * ldB + k0 + c4 * 8, true);
        }
        asm volatile("cp.async.commit_group;" ::: "memory");
    };

    loadStage(0, 0);
    if (nIter > 1) loadStage(1, 1);
    for (int it = 0; it < nIter; ++it) {
        int cur = it % NSTG;
        if (it + 2 < nIter) {
            loadStage(it + 2, (it + 2) % NSTG);
            asm volatile("cp.async.wait_group 2;" ::: "memory");
        } else if (it + 1 < nIter) {
            asm volatile("cp.async.wait_group 1;" ::: "memory");
        } else {
            asm volatile("cp.async.wait_group 0;" ::: "memory");
        }
        __syncthreads();

        const __half* Ash = smemh + cur * STGH;
        const __half* Bsh = Ash + 128 * ASTH;
        bool ms = (((it * 32) >> 7) == meanSeg);
        if (ms) mma_block_h<true >(Ash, Bsh, acc, wm, wn, fr, fc, fs);
        else    mma_block_h<false>(Ash, Bsh, acc, wm, wn, fr, fc, fs);
        __syncthreads();
    }

    #pragma unroll
    for (int mt = 0; mt < 2; mt++) {
        #pragma unroll
        for (int nt = 0; nt < 8; nt++) {
            int r0 = bm + wm + mt * 16 + fr;
            int cc = wn + nt * 8 + 2 * fc;
            float b0 = 0.f, b1 = 0.f;
            if (bias) { b0 = bias[cc]; b1 = bias[cc + 1]; }
            float v0 = acc[mt][nt][0] + b0, v1 = acc[mt][nt][1] + b1;
            float v2 = acc[mt][nt][2] + b0, v3 = acc[mt][nt][3] + b1;
            if (relu) {
                v0 = fmaxf(v0, 0.f); v1 = fmaxf(v1, 0.f);
                v2 = fmaxf(v2, 0.f); v3 = fmaxf(v3, 0.f);
            }
            if (r0 < M)
                *(unsigned*)(out + (size_t)r0 * 128 + cc) = pack_h2(v0, v1);
            if (r0 + 8 < M)
                *(unsigned*)(out + (size_t)(r0 + 8) * 128 + cc) = pack_h2(v2, v3);
        }
    }
}

// ---------------- fp16 MMA output projection: out = H2h @ WoT^T + b ---------
#define OASTH 136
#define OBSTH 136
#define OSMEM_BYTES ((128 * OASTH + 40 * OBSTH) * 2)   // 45696

__global__ __launch_bounds__(256, 2)
void out_gemm(const __half* __restrict__ H2h, const __half* __restrict__ WoT,
              const float* __restrict__ bias, float* __restrict__ out, int M) {
    extern __shared__ __half smemh[];
    __half* Ash = smemh;
    __half* Bsh = smemh + 128 * OASTH;
    const int tid = threadIdx.x;
    const int bm = blockIdx.x * 128;
    const int lane = tid & 31, wid = tid >> 5;
    const int fr = lane >> 2, fc = lane & 3;

    #pragma unroll
    for (int i = 0; i < 8; i++) {
        int id = tid + 256 * i;
        int row = id >> 4, c4 = id & 15;
        bool p = (bm + row) < M;
        cpasync16(Ash + row * OASTH + c4 * 8,
                  H2h + (size_t)(bm + row) * 128 + c4 * 8, p);
    }
    #pragma unroll
    for (int i = 0; i < 3; i++) {
        int id = tid + 256 * i;
        if (id < 40 * 16) {
            int row = id >> 4, c4 = id & 15;
            cpasync16(Bsh + row * OBSTH + c4 * 8,
                      WoT + (size_t)row * 128 + c4 * 8, true);
        }
    }
    asm volatile("cp.async.commit_group;" ::: "memory");
    asm volatile("cp.async.wait_group 0;" ::: "memory");
    __syncthreads();

    const int m0 = wid * 16;
    float acc[5][4];
    #pragma unroll
    for (int nt = 0; nt < 5; nt++)
        #pragma unroll
        for (int j = 0; j < 4; j++) acc[nt][j] = 0.f;

    #pragma unroll
    for (int ks = 0; ks < 128; ks += 16) {
        unsigned a[4];
        a[0] = *(const unsigned*)&Ash[(m0 + fr)     * OASTH + ks + 2 * fc];
        a[1] = *(const unsigned*)&Ash[(m0 + fr + 8) * OASTH + ks + 2 * fc];
        a[2] = *(const unsigned*)&Ash[(m0 + fr)     * OASTH + ks + 2 * fc + 8];
        a[3] = *(const unsigned*)&Ash[(m0 + fr + 8) * OASTH + ks + 2 * fc + 8];
        #pragma unroll
        for (int nt = 0; nt < 5; nt++) {
            int n = nt * 8 + fr;
            unsigned b0 = *(const unsigned*)&Bsh[n * OBSTH + ks + 2 * fc];
            unsigned b1 = *(const unsigned*)&Bsh[n * OBSTH + ks + 2 * fc + 8];
            mma_f16(acc[nt], a, b0, b1);
        }
    }

    #pragma unroll
    for (int nt = 0; nt < 5; nt++) {
        int r0 = bm + m0 + fr;
        int cc = nt * 8 + 2 * fc;
        float b0 = bias[cc], b1 = bias[cc + 1];
        if (r0 < M) {
            float2 o = make_float2(acc[nt][0] + b0, acc[nt][1] + b1);
            *(float2*)(out + (size_t)r0 * CLS + cc) = o;
        }
        if (r0 + 8 < M) {
            float2 o = make_float2(acc[nt][2] + b0, acc[nt][3] + b1);
            *(float2*)(out + (size_t)(r0 + 8) * CLS + cc) = o;
        }
    }
}

// ---------------- host side -------------------------------------------------
extern "C" void kernel_launch(void* const* d_in, const int* in_sizes, int n_in,
                              void* d_out, int out_size) {
    const float* x      = (const float*)d_in[0];
    const int*   ei     = (const int*)  d_in[1];
    const float* w1_pre = (const float*)d_in[2];
    const float* b1_pre = (const float*)d_in[3];
    const float* w1_post= (const float*)d_in[4];
    const float* b1_post= (const float*)d_in[5];
    const float* w1_lin = (const float*)d_in[6];
    const float* b1_lin = (const float*)d_in[7];
    const float* w2_pre = (const float*)d_in[8];
    const float* b2_pre = (const float*)d_in[9];
    const float* w2_post= (const float*)d_in[10];
    const float* b2_post= (const float*)d_in[11];
    const float* w2_lin = (const float*)d_in[12];
    const float* b2_lin = (const float*)d_in[13];
    const float* w_out  = (const float*)d_in[14];
    const float* b_out  = (const float*)d_in[15];
    float* out = (float*)d_out;

    static int init_done = 0;
    if (!init_done) {
        cudaFuncSetAttribute(mma_gemm, cudaFuncAttributeMaxDynamicSharedMemorySize,
                             GSMEM_BYTES);
        cudaFuncSetAttribute(out_gemm, cudaFuncAttributeMaxDynamicSharedMemorySize,
                             OSMEM_BYTES);
        init_done = 1;
    }

    void *pXh, *pAh, *pBh, *pSh, *pMh, *pHh, *pH2h, *pIC, *pWpreH,
         *pWfT1, *pWfT2, *pWfb1, *pWfb2, *pWoTh, *pHist;
    cudaGetSymbolAddress(&pXh, g_Xh);
    cudaGetSymbolAddress(&pAh, g_Ah);
    cudaGetSymbolAddress(&pBh, g_Bh);
    cudaGetSymbolAddress(&pSh, g_Sh);
    cudaGetSymbolAddress(&pMh, g_Mh);
    cudaGetSymbolAddress(&pHh, g_Hh);
    cudaGetSymbolAddress(&pH2h, g_H2h);
    cudaGetSymbolAddress(&pIC, g_IC);
    cudaGetSymbolAddress(&pWpreH, g_WpreH);
    cudaGetSymbolAddress(&pWfT1, g_WfT1);
    cudaGetSymbolAddress(&pWfT2, g_WfT2);
    cudaGetSymbolAddress(&pWfb1, g_Wfb1);
    cudaGetSymbolAddress(&pWfb2, g_Wfb2);
    cudaGetSymbolAddress(&pWoTh, g_WoTh);
    cudaGetSymbolAddress(&pHist, g_hist);

    const int* srcp = ei;           // edge_index[0]
    const int* dstp = ei + NEDGES;  // edge_index[1]

    // ---- graph preprocessing (single stream) --------------------------------
    cudaMemsetAsync(pHist, 0, NNODES * sizeof(int));
    hist_kernel<<<(NEDGES + 255) / 256, 256>>>(dstp);
    scanA_kernel<<<SCAN_B, 256>>>();
    scanB_kernel<<<1, 256>>>();
    scanC_kernel<<<SCAN_B, 256>>>();
    scatter_kernel<<<(NEDGES + 255) / 256, 256>>>(srcp, dstp);

    // ---- input + weight preprocessing (merged) ------------------------------
    prep_all<<<(PREP_TOTAL + 255) / 256, 256>>>(x, w1_pre, w2_pre, w_out);
    fuse_kernel<<<130, 128>>>(w1_post, b1_post, w1_lin, b1_lin,
                              w2_post, b2_post, w2_lin, b2_lin,
                              (__half*)pWfT1, (float*)pWfb1,
                              (__half*)pWfT2, (float*)pWfb2);

    const int MB = (NNODES + 127) / 128;
    const int AGG_BLOCKS = (NNODES + 15) / 16;   // 16 nodes per 256-thread block

    // ---- layer 1 -----------------------------------------------------------
    GemmSrcs pre1;
    pre1.s[0] = (const __half*)pXh; pre1.s[1] = pre1.s[0];
    pre1.s[2] = pre1.s[0]; pre1.s[3] = pre1.s[0];
    mma_gemm<<<dim3(2, MB), 256, GSMEM_BYTES>>>(
        pre1, (const __half*)pWpreH, b1_pre, (__half*)pAh, (__half*)pBh,
        nullptr, -1, NNODES, 128 / 32, 0, 128);
    aggregate_kernel<<<AGG_BLOCKS, 256>>>();

    GemmSrcs cat1;
    cat1.s[0] = (const __half*)pXh; cat1.s[1] = (const __half*)pSh;
    cat1.s[2] = (const __half*)pMh; cat1.s[3] = (const __half*)pSh;
    mma_gemm<<<dim3(1, MB), 256, GSMEM_BYTES>>>(
        cat1, (const __half*)pWfT1, (const float*)pWfb1,
        (__half*)pHh, (__half*)pHh, (const float*)pIC, 1, NNODES, 512 / 32, 1, 512);

    // ---- layer 2 -----------------------------------------------------------
    GemmSrcs pre2;
    pre2.s[0] = (const __half*)pHh; pre2.s[1] = pre2.s[0];
    pre2.s[2] = pre2.s[0]; pre2.s[3] = pre2.s[0];
    mma_gemm<<<dim3(2, MB), 256, GSMEM_BYTES>>>(
        pre2, (const __half*)pWpreH + 2 * 128 * 128, b2_pre, (__half*)pAh, (__half*)pBh,
        nullptr, -1, NNODES, 128 / 32, 0, 128);
    aggregate_kernel<<<AGG_BLOCKS, 256>>>();

    GemmSrcs cat2;
    cat2.s[0] = (const __half*)pHh; cat2.s[1] = (const __half*)pSh;
    cat2.s[2] = (const __half*)pMh; cat2.s[3] = (const __half*)pSh;
    mma_gemm<<<dim3(1, MB), 256, GSMEM_BYTES>>>(
        cat2, (const __half*)pWfT2, (const float*)pWfb2,
        (__half*)pH2h, (__half*)pH2h, (const float*)pIC, 1, NNODES, 512 / 32, 1, 512);

    // ---- output projection (fp16 MMA) ---------------------------------------
    out_gemm<<<(NNODES + 127) / 128, 256, OSMEM_BYTES>>>(
        (const __half*)pH2h, (const __half*)pWoTh, b_out, out, NNODES);
}

// round 17
// speedup vs baseline: 1.5423x; 1.0671x over previous
#include <cuda_runtime.h>
#include <cuda_fp16.h>
#include <math.h>
#include <stdint.h>

#define NNODES 50000
#define NEDGES 500000
#define FDIM   128
#define CLS    40

// ---------------- scratch (static device globals; no allocation) ------------
__device__ __half g_Xh  [NNODES * FDIM];   // fp16 copy of x
__device__ __half g_Ah  [NNODES * FDIM];   // A' = x @ W_top + b_pre (fp16)
__device__ __half g_Bh  [NNODES * FDIM];   // B  = x @ W_bot        (fp16)
__device__ __half g_Sh  [NNODES * FDIM];   // SUM aggregator  (fp16)
__device__ __half g_Mh  [NNODES * FDIM];   // MAX aggregator  (fp16)
__device__ __half g_Hh  [NNODES * FDIM];   // hidden after layer 1 (fp16)
__device__ float  g_IC  [NNODES + 128];    // 1/max(cnt,1) per node (padded)
__device__ __half g_WpreH[2 * 2 * FDIM * FDIM]; // [layer][half][n][k] fp16 transposed
__device__ __half g_WfT1[FDIM * 512];      // fused W' layer 1, [n][k] fp16 transposed
__device__ __half g_WfT2[FDIM * 512];      // fused W' layer 2, [n][k] fp16 transposed
__device__ float  g_Wfb1[FDIM];            // fused bias layer 1 (fp32)
__device__ float  g_Wfb2[FDIM];            // fused bias layer 2 (fp32)
__device__ __half g_WoTh[CLS * FDIM];      // w_out transposed [n][k] fp16
__device__ int    g_hist[NNODES];
__device__ int    g_off [NNODES + 1];
__device__ int    g_cur [NNODES];          // scatter cursor (init = offset)
__device__ int    g_ssrc[NEDGES];          // src ids grouped (counting-sorted) by dst
#define SCAN_B 196                          // ceil(50000/256)
__device__ int    g_bsum[SCAN_B];
__device__ int    g_boff[SCAN_B];

// ---------------- helpers ---------------------------------------------------
__device__ __forceinline__ unsigned pack_h2(float lo, float hi) {
    __half2 h = __floats2half2_rn(lo, hi);   // .x = lo (low 16 bits) = lower k
    return *reinterpret_cast<unsigned*>(&h);
}

__device__ __forceinline__ void cpasync16(void* dst, const void* src, bool pred) {
    unsigned sa = (unsigned)__cvta_generic_to_shared(dst);
    int sz = pred ? 16 : 0;
    asm volatile("cp.async.cg.shared.global [%0], [%1], 16, %2;\n"
                 :: "r"(sa), "l"(src), "r"(sz));
}

// fp16 MMA, fp32 accumulate: D(16x8) += A(16x16) * B(16x8)
__device__ __forceinline__ void mma_f16(float* c, const unsigned* a,
                                        unsigned b0, unsigned b1) {
    asm volatile(
        "mma.sync.aligned.m16n8k16.row.col.f32.f16.f16.f32 "
        "{%0,%1,%2,%3}, {%4,%5,%6,%7}, {%8,%9}, {%0,%1,%2,%3};"
        : "+f"(c[0]), "+f"(c[1]), "+f"(c[2]), "+f"(c[3])
        : "r"(a[0]), "r"(a[1]), "r"(a[2]), "r"(a[3]), "r"(b0), "r"(b1));
}

// ---------------- graph preprocessing ---------------------------------------
__global__ void hist_kernel(const int* __restrict__ dst) {
    int i = blockIdx.x * blockDim.x + threadIdx.x;
    if (i < NEDGES) atomicAdd(&g_hist[dst[i]], 1);
}

// scanA: per-block sums via shuffle reduce (1 sync)
__global__ void scanA_kernel() {
    int b = blockIdx.x, t = threadIdx.x;
    int i = b * 256 + t;
    int v = (i < NNODES) ? g_hist[i] : 0;
    #pragma unroll
    for (int d = 16; d > 0; d >>= 1) v += __shfl_down_sync(0xffffffffu, v, d);
    __shared__ int ws[8];
    if ((t & 31) == 0) ws[t >> 5] = v;
    __syncthreads();
    if (t == 0) {
        int s = 0;
        #pragma unroll
        for (int w = 0; w < 8; w++) s += ws[w];
        g_bsum[b] = s;
    }
}

// scanB: exclusive scan of SCAN_B block sums (shuffle, 2 syncs)
__global__ void scanB_kernel() {
    int t = threadIdx.x;
    int v = (t < SCAN_B) ? g_bsum[t] : 0;
    int lane = t & 31, w = t >> 5;
    int x = v;
    #pragma unroll
    for (int d = 1; d < 32; d <<= 1) {
        int y = __shfl_up_sync(0xffffffffu, x, d);
        if (lane >= d) x += y;
    }
    __shared__ int ws[8];
    if (lane == 31) ws[w] = x;
    __syncthreads();
    if (w == 0) {
        int wv = (lane < 8) ? ws[lane] : 0;
        #pragma unroll
        for (int d = 1; d < 8; d <<= 1) {
            int y = __shfl_up_sync(0xffffffffu, wv, d);
            if (lane >= d) wv += y;
        }
        if (lane < 8) ws[lane] = wv;
    }
    __syncthreads();
    int base = (w > 0) ? ws[w - 1] : 0;
    int incl = base + x;
    if (t < SCAN_B) g_boff[t] = incl - v;   // exclusive
}

// scanC: final offsets; also initializes the scatter cursor (g_cur = offset)
__global__ void scanC_kernel() {
    int b = blockIdx.x, t = threadIdx.x;
    int i = b * 256 + t;
    int v = (i < NNODES) ? g_hist[i] : 0;
    int lane = t & 31, w = t >> 5;
    int x = v;
    #pragma unroll
    for (int d = 1; d < 32; d <<= 1) {
        int y = __shfl_up_sync(0xffffffffu, x, d);
        if (lane >= d) x += y;
    }
    __shared__ int ws[8];
    if (lane == 31) ws[w] = x;
    __syncthreads();
    if (w == 0) {
        int wv = (lane < 8) ? ws[lane] : 0;
        #pragma unroll
        for (int d = 1; d < 8; d <<= 1) {
            int y = __shfl_up_sync(0xffffffffu, wv, d);
            if (lane >= d) wv += y;
        }
        if (lane < 8) ws[lane] = wv;
    }
    __syncthreads();
    int base = ((w > 0) ? ws[w - 1] : 0) + g_boff[b];
    int excl = base + x - v;
    if (i < NNODES) { g_off[i] = excl; g_cur[i] = excl; }
    if (b == 0 && t == 0) g_off[NNODES] = NEDGES;
}

__global__ void scatter_kernel(const int* __restrict__ src, const int* __restrict__ dst) {
    int i = blockIdx.x * blockDim.x + threadIdx.x;
    if (i >= NEDGES) return;
    int p = atomicAdd(&g_cur[dst[i]], 1);   // cursor holds absolute position
    g_ssrc[p] = src[i];
}

// ---------------- merged input + weight preprocessing ------------------------
#define CVT_X_N (NNODES * FDIM / 4)             // 1,600,000
#define PREP_W  (2 * 2 * FDIM * FDIM)           // 65536
#define PREP_O  (CLS * FDIM)                    // 5120
#define PREP_TOTAL (CVT_X_N + PREP_W + PREP_O)
__global__ void prep_all(const float* __restrict__ x,
                         const float* __restrict__ w1,
                         const float* __restrict__ w2,
                         const float* __restrict__ wo) {
    int i = blockIdx.x * blockDim.x + threadIdx.x;
    if (i < CVT_X_N) {
        float4 v = __ldg(&((const float4*)x)[i]);
        uint2 o;
        o.x = pack_h2(v.x, v.y);
        o.y = pack_h2(v.z, v.w);
        ((uint2*)g_Xh)[i] = o;
    } else if (i < CVT_X_N + PREP_W) {
        int j = i - CVT_X_N;
        int k = j & 127;
        int n = (j >> 7) & 127;
        int h = (j >> 14) & 1;
        int l = j >> 15;
        const float* w = l ? w2 : w1;
        g_WpreH[j] = __float2half_rn(__ldg(&w[(h * 128 + k) * 128 + n]));
    } else if (i < PREP_TOTAL) {
        int j = i - CVT_X_N - PREP_W;
        int n = j >> 7, k = j & 127;
        g_WoTh[j] = __float2half_rn(__ldg(&wo[k * CLS + n]));
    }
}

// ---------------- aggregation: 2 nodes/warp, uint4 gather, unroll 8 ----------
__global__ void aggregate_kernel() {
    int gw = (blockIdx.x * blockDim.x + threadIdx.x) >> 5;
    int lane = threadIdx.x & 31;
    int node = gw * 2 + (lane >> 4);
    if (node >= NNODES) return;
    int l16 = lane & 15;
    int beg = g_off[node], end = g_off[node + 1];
    const uint4* Bv = (const uint4*)g_Bh;        // 16 uint4 per row
    float s[8] = {0.f, 0.f, 0.f, 0.f, 0.f, 0.f, 0.f, 0.f};
    float m[8];
    #pragma unroll
    for (int i = 0; i < 8; i++) m[i] = -3.4e38f;
    int e = beg;
    for (; e + 7 < end; e += 8) {
        int sv[8];
        #pragma unroll
        for (int j = 0; j < 8; j++) sv[j] = __ldg(&g_ssrc[e + j]);
        uint4 r[8];
        #pragma unroll
        for (int j = 0; j < 8; j++) r[j] = __ldg(&Bv[(size_t)sv[j] * 16 + l16]);
        #pragma unroll
        for (int j = 0; j < 8; j++) {
            float2 p0 = __half22float2(*(__half2*)&r[j].x);
            float2 p1 = __half22float2(*(__half2*)&r[j].y);
            float2 p2 = __half22float2(*(__half2*)&r[j].z);
            float2 p3 = __half22float2(*(__half2*)&r[j].w);
            s[0] += p0.x; s[1] += p0.y; s[2] += p1.x; s[3] += p1.y;
            s[4] += p2.x; s[5] += p2.y; s[6] += p3.x; s[7] += p3.y;
            m[0] = fmaxf(m[0], p0.x); m[1] = fmaxf(m[1], p0.y);
            m[2] = fmaxf(m[2], p1.x); m[3] = fmaxf(m[3], p1.y);
            m[4] = fmaxf(m[4], p2.x); m[5] = fmaxf(m[5], p2.y);
            m[6] = fmaxf(m[6], p3.x); m[7] = fmaxf(m[7], p3.y);
        }
    }
    for (; e < end; e++) {
        int sv = __ldg(&g_ssrc[e]);
        uint4 r = __ldg(&Bv[(size_t)sv * 16 + l16]);
        float2 p0 = __half22float2(*(__half2*)&r.x);
        float2 p1 = __half22float2(*(__half2*)&r.y);
        float2 p2 = __half22float2(*(__half2*)&r.z);
        float2 p3 = __half22float2(*(__half2*)&r.w);
        s[0] += p0.x; s[1] += p0.y; s[2] += p1.x; s[3] += p1.y;
        s[4] += p2.x; s[5] += p2.y; s[6] += p3.x; s[7] += p3.y;
        m[0] = fmaxf(m[0], p0.x); m[1] = fmaxf(m[1], p0.y);
        m[2] = fmaxf(m[2], p1.x); m[3] = fmaxf(m[3], p1.y);
        m[4] = fmaxf(m[4], p2.x); m[5] = fmaxf(m[5], p2.y);
        m[6] = fmaxf(m[6], p3.x); m[7] = fmaxf(m[7], p3.y);
    }
    size_t o = (size_t)node * 16 + l16;   // uint4 index: cols 8*l16..8*l16+7
    float c = (float)(end - beg);
    float ic = 1.f / fmaxf(c, 1.f);
    if (l16 == 0) g_IC[node] = ic;
    uint4 ar = ((const uint4*)g_Ah)[o];
    float2 a0 = __half22float2(*(__half2*)&ar.x);
    float2 a1 = __half22float2(*(__half2*)&ar.y);
    float2 a2 = __half22float2(*(__half2*)&ar.z);
    float2 a3 = __half22float2(*(__half2*)&ar.w);
    float av[8] = {a0.x, a0.y, a1.x, a1.y, a2.x, a2.y, a3.x, a3.y};
    uint4 so;
    so.x = pack_h2(fmaf(c, av[0], s[0]), fmaf(c, av[1], s[1]));
    so.y = pack_h2(fmaf(c, av[2], s[2]), fmaf(c, av[3], s[3]));
    so.z = pack_h2(fmaf(c, av[4], s[4]), fmaf(c, av[5], s[5]));
    so.w = pack_h2(fmaf(c, av[6], s[6]), fmaf(c, av[7], s[7]));
    ((uint4*)g_Sh)[o] = so;
    bool nz = (c > 0.f);
    uint4 mo;
    mo.x = pack_h2(nz ? (av[0] + m[0]) : 0.f, nz ? (av[1] + m[1]) : 0.f);
    mo.y = pack_h2(nz ? (av[2] + m[2]) : 0.f, nz ? (av[3] + m[3]) : 0.f);
    mo.z = pack_h2(nz ? (av[4] + m[4]) : 0.f, nz ? (av[5] + m[5]) : 0.f);
    mo.w = pack_h2(nz ? (av[6] + m[6]) : 0.f, nz ? (av[7] + m[7]) : 0.f);
    ((uint4*)g_Mh)[o] = mo;
}

// ---------------- fused post@lin weight (both layers, one launch) ------------
__global__ void fuse_kernel(const float* __restrict__ w1post, const float* __restrict__ b1post,
                            const float* __restrict__ w1lin,  const float* __restrict__ b1lin,
                            const float* __restrict__ w2post, const float* __restrict__ b2post,
                            const float* __restrict__ w2lin,  const float* __restrict__ b2lin,
                            __half* __restrict__ wfT1, float* __restrict__ wfb1,
                            __half* __restrict__ wfT2, float* __restrict__ wfb2) {
    __shared__ float srow[8][FDIM];
    int bb = blockIdx.x;
    int layer = (bb >= 65);
    int b = bb - layer * 65;
    const float* wpost = layer ? w2post : w1post;
    const float* bpost = layer ? b2post : b1post;
    const float* wlin  = layer ? w2lin  : w1lin;
    const float* blin  = layer ? b2lin  : b1lin;
    __half* wfT = layer ? wfT2 : wfT1;
    float* wfb  = layer ? wfb2 : wfb1;
    const int c = threadIdx.x;   // 128 threads
    if (b < 64) {
        #pragma unroll
        for (int j = 0; j < 8; j++)
            srow[j][c] = wpost[(size_t)(8 * b + j) * FDIM + c];
        __syncthreads();
        float acc[8] = {};
        #pragma unroll 4
        for (int k = 0; k < FDIM; k++) {
            float wl = wlin[k * FDIM + c];
            #pragma unroll
            for (int j = 0; j < 8; j++) acc[j] = fmaf(srow[j][k], wl, acc[j]);
        }
        #pragma unroll
        for (int j = 0; j < 8; j++)
            wfT[(size_t)c * 512 + 8 * b + j] = __float2half_rn(acc[j]);
    } else {
        srow[0][c] = bpost[c];
        __syncthreads();
        float acc = blin[c];
        #pragma unroll 4
        for (int k = 0; k < FDIM; k++) acc = fmaf(srow[0][k], wlin[k * FDIM + c], acc);
        wfb[c] = acc;
    }
}

// ---------------- persistent-A pre-GEMM --------------------------------------
// A tile (128x128 fp16) resident in smem; B slabs pipelined (3 stages).
// Iterates both weight halves: epilogue at it=3 -> A'(+bias), it=7 -> B.
// Removes the duplicated A read of the old dual-block scheme. Bit-identical.
#define PASTH 136                               // A row stride (halves)
#define PBSTH 72                                // B row stride (halves)
#define PB_STG (128 * PBSTH)                    // 9216 halves per stage
#define PRE_SMEM_BYTES ((128 * PASTH + 3 * PB_STG) * 2)   // 90112

__global__ __launch_bounds__(256, 2)
void pre_gemm(const __half* __restrict__ Xin, const __half* __restrict__ W,
              const float* __restrict__ bias,
              __half* __restrict__ outA, __half* __restrict__ outB, int M) {
    extern __shared__ __half smemh[];
    __half* Ash = smemh;                        // 128 x PASTH
    __half* Bst = smemh + 128 * PASTH;          // 3 B stages
    const int tid = threadIdx.x;
    const int bm = blockIdx.x * 128;
    const int lane = tid & 31, wid = tid >> 5;
    const int wm = (wid >> 1) * 32, wn = (wid & 1) * 64;
    const int fr = lane >> 2, fc = lane & 3;

    // A tile: 128 rows x 128 halves = 2048 16B chunks, 8 iters
    #pragma unroll
    for (int i = 0; i < 8; i++) {
        int id = tid + 256 * i;
        int row = id >> 4, c4 = id & 15;
        bool p = (bm + row) < M;
        cpasync16(Ash + row * PASTH + c4 * 8,
                  Xin + (size_t)(bm + row) * 128 + c4 * 8, p);
    }
    auto loadB = [&](int it, int stage) {       // it: 0..7 (h = it>>2, ks = it&3)
        int h = it >> 2, ks = it & 3;
        __half* Bsh = Bst + stage * PB_STG;
        #pragma unroll
        for (int i = 0; i < 2; i++) {
            int id = tid + 256 * i;
            int n = id >> 2, c4 = id & 3;
            cpasync16(Bsh + n * PBSTH + c4 * 8,
                      W + (size_t)h * 128 * 128 + (size_t)n * 128 + ks * 32 + c4 * 8,
                      true);
        }
        asm volatile("cp.async.commit_group;" ::: "memory");
    };
    loadB(0, 0);        // group 0 = A tile + B slab 0
    loadB(1, 1);        // group 1 = B slab 1

    float acc[2][8][4];
    #pragma unroll
    for (int mt = 0; mt < 2; mt++)
        #pragma unroll
        for (int nt = 0; nt < 8; nt++)
            #pragma unroll
            for (int j = 0; j < 4; j++) acc[mt][nt][j] = 0.f;

    for (int it = 0; it < 8; ++it) {
        int cur = it % 3;
        if (it + 2 < 8) {
            loadB(it + 2, (it + 2) % 3);
            asm volatile("cp.async.wait_group 2;" ::: "memory");
        } else if (it + 1 < 8) {
            asm volatile("cp.async.wait_group 1;" ::: "memory");
        } else {
            asm volatile("cp.async.wait_group 0;" ::: "memory");
        }
        __syncthreads();

        const __half* Bsh = Bst + cur * PB_STG;
        const int kbase = (it & 3) * 32;
        #pragma unroll
        for (int ks = 0; ks < 32; ks += 16) {
            unsigned a[2][4];
            #pragma unroll
            for (int mt = 0; mt < 2; mt++) {
                int r0 = wm + mt * 16 + fr;
                a[mt][0] = *(const unsigned*)&Ash[(r0)     * PASTH + kbase + ks + 2 * fc];
                a[mt][1] = *(const unsigned*)&Ash[(r0 + 8) * PASTH + kbase + ks + 2 * fc];
                a[mt][2] = *(const unsigned*)&Ash[(r0)     * PASTH + kbase + ks + 2 * fc + 8];
                a[mt][3] = *(const unsigned*)&Ash[(r0 + 8) * PASTH + kbase + ks + 2 * fc + 8];
            }
            #pragma unroll
            for (int nt = 0; nt < 8; nt++) {
                int n = wn + nt * 8 + fr;
                unsigned b0 = *(const unsigned*)&Bsh[n * PBSTH + ks + 2 * fc];
                unsigned b1 = *(const unsigned*)&Bsh[n * PBSTH + ks + 2 * fc + 8];
                mma_f16(acc[0][nt], a[0], b0, b1);
                mma_f16(acc[1][nt], a[1], b0, b1);
            }
        }
        __syncthreads();

        if (it == 3 || it == 7) {               // epilogue per weight half
            int h = it >> 2;
            __half* out = h ? outB : outA;
            #pragma unroll
            for (int mt = 0; mt < 2; mt++) {
                #pragma unroll
                for (int nt = 0; nt < 8; nt++) {
                    int r0 = bm + wm + mt * 16 + fr;
                    int cc = wn + nt * 8 + 2 * fc;
                    float b0 = 0.f, b1 = 0.f;
                    if (h == 0) { b0 = bias[cc]; b1 = bias[cc + 1]; }
                    float v0 = acc[mt][nt][0] + b0, v1 = acc[mt][nt][1] + b1;
                    float v2 = acc[mt][nt][2] + b0, v3 = acc[mt][nt][3] + b1;
                    if (r0 < M)
                        *(unsigned*)(out + (size_t)r0 * 128 + cc) = pack_h2(v0, v1);
                    if (r0 + 8 < M)
                        *(unsigned*)(out + (size_t)(r0 + 8) * 128 + cc) = pack_h2(v2, v3);
                    acc[mt][nt][0] = 0.f; acc[mt][nt][1] = 0.f;
                    acc[mt][nt][2] = 0.f; acc[mt][nt][3] = 0.f;
                }
            }
        }
    }
}

// ---------------- fp16 cat-GEMM (3-stage pipeline; optional fused out-proj) --
#define ASTH 40              // A smem row stride (halves): 32 + 8 pad
#define BSTH 72              // B smem row stride (halves): 64 + 8 pad
#define STGH (128 * ASTH + 128 * BSTH)      // halves per stage = 14336
#define NSTG 3
#define GSMEM_BYTES (NSTG * STGH * 2)       // 86016 (>= fused-out need 45696)
#define OASTH 136            // fused out-proj: H2 smem row stride (halves)

struct GemmSrcs { const __half* s[4]; };

template<bool SCALE>
__device__ __forceinline__ void mma_block_h(const __half* __restrict__ Ash,
                                            const __half* __restrict__ Bsh,
                                            float (*acc)[8][4],
                                            int wm, int wn, int fr, int fc,
                                            const float* fs) {
    #pragma unroll
    for (int ks = 0; ks < 32; ks += 16) {
        unsigned a[2][4];
        #pragma unroll
        for (int mt = 0; mt < 2; mt++) {
            int r0 = wm + mt * 16 + fr;
            unsigned u0 = *(const unsigned*)&Ash[(r0)     * ASTH + ks + 2 * fc];
            unsigned u1 = *(const unsigned*)&Ash[(r0 + 8) * ASTH + ks + 2 * fc];
            unsigned u2 = *(const unsigned*)&Ash[(r0)     * ASTH + ks + 2 * fc + 8];
            unsigned u3 = *(const unsigned*)&Ash[(r0 + 8) * ASTH + ks + 2 * fc + 8];
            if (SCALE) {
                float f0 = fs[mt * 2], f1 = fs[mt * 2 + 1];
                float2 p0 = __half22float2(*(__half2*)&u0);
                float2 p1 = __half22float2(*(__half2*)&u1);
                float2 p2 = __half22float2(*(__half2*)&u2);
                float2 p3 = __half22float2(*(__half2*)&u3);
                u0 = pack_h2(p0.x * f0, p0.y * f0);
                u1 = pack_h2(p1.x * f1, p1.y * f1);
                u2 = pack_h2(p2.x * f0, p2.y * f0);
                u3 = pack_h2(p3.x * f1, p3.y * f1);
            }
            a[mt][0] = u0; a[mt][1] = u1; a[mt][2] = u2; a[mt][3] = u3;
        }
        #pragma unroll
        for (int nt = 0; nt < 8; nt++) {
            int n = wn + nt * 8 + fr;
            unsigned b0 = *(const unsigned*)&Bsh[n * BSTH + ks + 2 * fc];
            unsigned b1 = *(const unsigned*)&Bsh[n * BSTH + ks + 2 * fc + 8];
            mma_f16(acc[0][nt], a[0], b0, b1);
            mma_f16(acc[1][nt], a[1], b0, b1);
        }
    }
}

__global__ __launch_bounds__(256, 2)
void mma_gemm(GemmSrcs srcs, const __half* __restrict__ W,
              const float* __restrict__ bias,
              __half* __restrict__ out,
              const float* __restrict__ icvec, int meanSeg,
              int M, int nIter, int relu,
              const __half* __restrict__ WoT,       // fused out-proj weights (or null)
              const float* __restrict__ outBias,
              float* __restrict__ outF) {
    extern __shared__ __half smemh[];
    const int tid = threadIdx.x;
    const int bm = blockIdx.y * 128;

    const int lane = tid & 31, wid = tid >> 5;
    const int wm = (wid >> 1) * 32, wn = (wid & 1) * 64;
    const int fr = lane >> 2, fc = lane & 3;

    float fs[4] = {1.f, 1.f, 1.f, 1.f};
    if (icvec) {
        int r = bm + wm + fr;
        fs[0] = icvec[r];      fs[1] = icvec[r + 8];
        fs[2] = icvec[r + 16]; fs[3] = icvec[r + 24];
    }

    float acc[2][8][4];
    #pragma unroll
    for (int mt = 0; mt < 2; mt++)
        #pragma unroll
        for (int nt = 0; nt < 8; nt++)
            #pragma unroll
            for (int j = 0; j < 4; j++) acc[mt][nt][j] = 0.f;

    auto loadStage = [&](int it, int stage) {
        int k0 = it * 32;
        const __half* sp = srcs.s[(k0 >> 7) & 3];
        int kloc = k0 & 127;
        __half* Ash = smemh + stage * STGH;
        __half* Bsh = Ash + 128 * ASTH;
        #pragma unroll
        for (int i = 0; i < 2; i++) {
            int id = tid + 256 * i;
            int arow = id >> 2, c4 = id & 3;
            bool p = (bm + arow) < M;
            cpasync16(Ash + arow * ASTH + c4 * 8,
                      sp + (size_t)(bm + arow) * 128 + kloc + c4 * 8, p);
        }
        #pragma unroll
        for (int i = 0; i < 2; i++) {
            int id = tid + 256 * i;
            int n = id >> 2, c4 = id & 3;
            cpasync16(Bsh + n * BSTH + c4 * 8,
                      W + (size_t)n * 512 + k0 + c4 * 8, true);
        }
        asm volatile("cp.async.commit_group;" ::: "memory");
    };

    loadStage(0, 0);
    if (nIter > 1) loadStage(1, 1);
    for (int it = 0; it < nIter; ++it) {
        int cur = it % NSTG;
        if (it + 2 < nIter) {
            loadStage(it + 2, (it + 2) % NSTG);
            asm volatile("cp.async.wait_group 2;" ::: "memory");
        } else if (it + 1 < nIter) {
            asm volatile("cp.async.wait_group 1;" ::: "memory");
        } else {
            asm volatile("cp.async.wait_group 0;" ::: "memory");
        }
        __syncthreads();

        const __half* Ash = smemh + cur * STGH;
        const __half* Bsh = Ash + 128 * ASTH;
        bool ms = (((it * 32) >> 7) == meanSeg);
        if (ms) mma_block_h<true >(Ash, Bsh, acc, wm, wn, fr, fc, fs);
        else    mma_block_h<false>(Ash, Bsh, acc, wm, wn, fr, fc, fs);
        __syncthreads();
    }

    if (!WoT) {
        // ---- normal epilogue: write fp16 H ----
        #pragma unroll
        for (int mt = 0; mt < 2; mt++) {
            #pragma unroll
            for (int nt = 0; nt < 8; nt++) {
                int r0 = bm + wm + mt * 16 + fr;
                int cc = wn + nt * 8 + 2 * fc;
                float b0 = bias[cc], b1 = bias[cc + 1];
                float v0 = acc[mt][nt][0] + b0, v1 = acc[mt][nt][1] + b1;
                float v2 = acc[mt][nt][2] + b0, v3 = acc[mt][nt][3] + b1;
                if (relu) {
                    v0 = fmaxf(v0, 0.f); v1 = fmaxf(v1, 0.f);
                    v2 = fmaxf(v2, 0.f); v3 = fmaxf(v3, 0.f);
                }
                if (r0 < M)
                    *(unsigned*)(out + (size_t)r0 * 128 + cc) = pack_h2(v0, v1);
                if (r0 + 8 < M)
                    *(unsigned*)(out + (size_t)(r0 + 8) * 128 + cc) = pack_h2(v2, v3);
            }
        }
        return;
    }

    // ---- fused out-projection: H2 tile -> smem (fp16, same rounding) -------
    __half* H2s = smemh;                    // 128 x OASTH halves
    __half* Wos = smemh + 128 * OASTH;      // 40 x OASTH halves
    #pragma unroll
    for (int mt = 0; mt < 2; mt++) {
        #pragma unroll
        for (int nt = 0; nt < 8; nt++) {
            int rl = wm + mt * 16 + fr;     // local row 0..127
            int cc = wn + nt * 8 + 2 * fc;
            float b0 = bias[cc], b1 = bias[cc + 1];
            float v0 = acc[mt][nt][0] + b0, v1 = acc[mt][nt][1] + b1;
            float v2 = acc[mt][nt][2] + b0, v3 = acc[mt][nt][3] + b1;
            v0 = fmaxf(v0, 0.f); v1 = fmaxf(v1, 0.f);
            v2 = fmaxf(v2, 0.f); v3 = fmaxf(v3, 0.f);
            *(unsigned*)&H2s[(size_t)rl * OASTH + cc] = pack_h2(v0, v1);
            *(unsigned*)&H2s[(size_t)(rl + 8) * OASTH + cc] = pack_h2(v2, v3);
        }
    }
    // load Wo (40 x 128 fp16, transposed [n][k])
    #pragma unroll
    for (int i = 0; i < 3; i++) {
        int id = tid + 256 * i;
        if (id < CLS * 16) {
            int row = id >> 4, c4 = id & 15;
            cpasync16(Wos + row * OASTH + c4 * 8,
                      WoT + (size_t)row * 128 + c4 * 8, true);
        }
    }
    asm volatile("cp.async.commit_group;" ::: "memory");
    asm volatile("cp.async.wait_group 0;" ::: "memory");
    __syncthreads();

    const int m0 = wid * 16;
    float oacc[5][4];
    #pragma unroll
    for (int nt = 0; nt < 5; nt++)
        #pragma unroll
        for (int j = 0; j < 4; j++) oacc[nt][j] = 0.f;

    #pragma unroll
    for (int ks = 0; ks < 128; ks += 16) {
        unsigned a[4];
        a[0] = *(const unsigned*)&H2s[(m0 + fr)     * OASTH + ks + 2 * fc];
        a[1] = *(const unsigned*)&H2s[(m0 + fr + 8) * OASTH + ks + 2 * fc];
        a[2] = *(const unsigned*)&H2s[(m0 + fr)     * OASTH + ks + 2 * fc + 8];
        a[3] = *(const unsigned*)&H2s[(m0 + fr + 8) * OASTH + ks + 2 * fc + 8];
        #pragma unroll
        for (int nt = 0; nt < 5; nt++) {
            int n = nt * 8 + fr;
            unsigned b0 = *(const unsigned*)&Wos[n * OASTH + ks + 2 * fc];
            unsigned b1 = *(const unsigned*)&Wos[n * OASTH + ks + 2 * fc + 8];
            mma_f16(oacc[nt], a, b0, b1);
        }
    }

    #pragma unroll
    for (int nt = 0; nt < 5; nt++) {
        int r0 = bm + m0 + fr;
        int cc = nt * 8 + 2 * fc;
        float b0 = outBias[cc], b1 = outBias[cc + 1];
        if (r0 < M) {
            float2 o = make_float2(oacc[nt][0] + b0, oacc[nt][1] + b1);
            *(float2*)(outF + (size_t)r0 * CLS + cc) = o;
        }
        if (r0 + 8 < M) {
            float2 o = make_float2(oacc[nt][2] + b0, oacc[nt][3] + b1);
            *(float2*)(outF + (size_t)(r0 + 8) * CLS + cc) = o;
        }
    }
}

// ---------------- host side -------------------------------------------------
extern "C" void kernel_launch(void* const* d_in, const int* in_sizes, int n_in,
                              void* d_out, int out_size) {
    const float* x      = (const float*)d_in[0];
    const int*   ei     = (const int*)  d_in[1];
    const float* w1_pre = (const float*)d_in[2];
    const float* b1_pre = (const float*)d_in[3];
    const float* w1_post= (const float*)d_in[4];
    const float* b1_post= (const float*)d_in[5];
    const float* w1_lin = (const float*)d_in[6];
    const float* b1_lin = (const float*)d_in[7];
    const float* w2_pre = (const float*)d_in[8];
    const float* b2_pre = (const float*)d_in[9];
    const float* w2_post= (const float*)d_in[10];
    const float* b2_post= (const float*)d_in[11];
    const float* w2_lin = (const float*)d_in[12];
    const float* b2_lin = (const float*)d_in[13];
    const float* w_out  = (const float*)d_in[14];
    const float* b_out  = (const float*)d_in[15];
    float* out = (float*)d_out;

    static int init_done = 0;
    if (!init_done) {
        cudaFuncSetAttribute(mma_gemm, cudaFuncAttributeMaxDynamicSharedMemorySize,
                             GSMEM_BYTES);
        cudaFuncSetAttribute(pre_gemm, cudaFuncAttributeMaxDynamicSharedMemorySize,
                             PRE_SMEM_BYTES);
        init_done = 1;
    }

    void *pXh, *pAh, *pBh, *pSh, *pMh, *pHh, *pIC, *pWpreH,
         *pWfT1, *pWfT2, *pWfb1, *pWfb2, *pWoTh, *pHist;
    cudaGetSymbolAddress(&pXh, g_Xh);
    cudaGetSymbolAddress(&pAh, g_Ah);
    cudaGetSymbolAddress(&pBh, g_Bh);
    cudaGetSymbolAddress(&pSh, g_Sh);
    cudaGetSymbolAddress(&pMh, g_Mh);
    cudaGetSymbolAddress(&pHh, g_Hh);
    cudaGetSymbolAddress(&pIC, g_IC);
    cudaGetSymbolAddress(&pWpreH, g_WpreH);
    cudaGetSymbolAddress(&pWfT1, g_WfT1);
    cudaGetSymbolAddress(&pWfT2, g_WfT2);
    cudaGetSymbolAddress(&pWfb1, g_Wfb1);
    cudaGetSymbolAddress(&pWfb2, g_Wfb2);
    cudaGetSymbolAddress(&pWoTh, g_WoTh);
    cudaGetSymbolAddress(&pHist, g_hist);

    const int* srcp = ei;           // edge_index[0]
    const int* dstp = ei + NEDGES;  // edge_index[1]

    // ---- graph preprocessing (single stream) --------------------------------
    cudaMemsetAsync(pHist, 0, NNODES * sizeof(int));
    hist_kernel<<<(NEDGES + 255) / 256, 256>>>(dstp);
    scanA_kernel<<<SCAN_B, 256>>>();
    scanB_kernel<<<1, 256>>>();
    scanC_kernel<<<SCAN_B, 256>>>();
    scatter_kernel<<<(NEDGES + 255) / 256, 256>>>(srcp, dstp);

    // ---- input + weight preprocessing ---------------------------------------
    prep_all<<<(PREP_TOTAL + 255) / 256, 256>>>(x, w1_pre, w2_pre, w_out);
    fuse_kernel<<<130, 128>>>(w1_post, b1_post, w1_lin, b1_lin,
                              w2_post, b2_post, w2_lin, b2_lin,
                              (__half*)pWfT1, (float*)pWfb1,
                              (__half*)pWfT2, (float*)pWfb2);

    const int MB = (NNODES + 127) / 128;
    const int AGG_BLOCKS = (NNODES + 15) / 16;

    // ---- layer 1 -----------------------------------------------------------
    pre_gemm<<<MB, 256, PRE_SMEM_BYTES>>>(
        (const __half*)pXh, (const __half*)pWpreH, b1_pre,
        (__half*)pAh, (__half*)pBh, NNODES);
    aggregate_kernel<<<AGG_BLOCKS, 256>>>();

    GemmSrcs cat1;
    cat1.s[0] = (const __half*)pXh; cat1.s[1] = (const __half*)pSh;
    cat1.s[2] = (const __half*)pMh; cat1.s[3] = (const __half*)pSh;
    mma_gemm<<<dim3(1, MB), 256, GSMEM_BYTES>>>(
        cat1, (const __half*)pWfT1, (const float*)pWfb1,
        (__half*)pHh, (const float*)pIC, 1, NNODES, 512 / 32, 1,
        (const __half*)nullptr, (const float*)nullptr, (float*)nullptr);

    // ---- layer 2 -----------------------------------------------------------
    pre_gemm<<<MB, 256, PRE_SMEM_BYTES>>>(
        (const __half*)pHh, (const __half*)pWpreH + 2 * 128 * 128, b2_pre,
        (__half*)pAh, (__half*)pBh, NNODES);
    aggregate_kernel<<<AGG_BLOCKS, 256>>>();

    GemmSrcs cat2;
    cat2.s[0] = (const __half*)pHh; cat2.s[1] = (const __half*)pSh;
    cat2.s[2] = (const __half*)pMh; cat2.s[3] = (const __half*)pSh;
    mma_gemm<<<dim3(1, MB), 256, GSMEM_BYTES>>>(
        cat2, (const __half*)pWfT2, (const float*)pWfb2,
        (__half*)nullptr, (const float*)pIC, 1, NNODES, 512 / 32, 1,
        (const __half*)pWoTh, b_out, out);
}